// round 9
// baseline (speedup 1.0000x reference)
#include <cuda_runtime.h>
#include <float.h>
#include <stdint.h>

#define BH 16
#define HH 8
#define NN 4096
#define DD 64
#define MM 256

// ---------------- scratch (__device__ globals; no allocation) ----------------
__device__ float g_nc [BH*MM*DD];
__device__ float g_nr [BH*MM*DD];
__device__ int   g_idxk[BH*MM];
__device__ int   g_idxq[BH*MM];
__device__ float g_u  [BH*MM*MM];
__device__ float g_v0 [BH*MM*MM];
__device__ float g_v1 [BH*MM*MM];
__device__ float g_kv [BH*MM*MM];
__device__ float g_t1 [BH*MM*MM];
__device__ float g_t2 [BH*MM*MM];
__device__ float g_nsp[2*BH*MM*MM];
__device__ float g_r  [(size_t)BH*MM*NN];   // 64 MB: kernel_3
__device__ float g_p  [(size_t)BH*NN*MM];   // 64 MB: kernel_1
__device__ float g_rvp[8*BH*MM*DD];
__device__ float g_rv [BH*MM*DD];
__device__ float g_y  [BH*MM*DD];

// ---------------- tf32 mma helpers ----------------
__device__ __forceinline__ uint32_t f2tf(float v) {
    uint32_t r; asm("cvt.rna.tf32.f32 %0, %1;" : "=r"(r) : "f"(v)); return r;
}
__device__ __forceinline__ void mma_tf32(float4& d, const uint32_t* a, const uint32_t* b) {
    asm volatile("mma.sync.aligned.m16n8k8.row.col.f32.tf32.tf32.f32 "
        "{%0,%1,%2,%3}, {%4,%5,%6,%7}, {%8,%9}, {%0,%1,%2,%3};"
        : "+f"(d.x), "+f"(d.y), "+f"(d.z), "+f"(d.w)
        : "r"(a[0]), "r"(a[1]), "r"(a[2]), "r"(a[3]), "r"(b[0]), "r"(b[1]));
}
__device__ __forceinline__ uint2 split_tf32(float x) {
    uint32_t hi = f2tf(x);
    float lo = x - __uint_as_float(hi);
    return make_uint2(hi, f2tf(lo));
}
// 3xTF32: d += a_hi*b_hi + a_lo*b_hi + a_hi*b_lo (fp32-grade)
__device__ __forceinline__ void mma_tf32x3(float4& d, const uint2* a, const uint2* b) {
    uint32_t ah[4] = {a[0].x, a[1].x, a[2].x, a[3].x};
    uint32_t al[4] = {a[0].y, a[1].y, a[2].y, a[3].y};
    uint32_t bh_[2] = {b[0].x, b[1].x};
    uint32_t bl_[2] = {b[0].y, b[1].y};
    mma_tf32(d, ah, bh_);
    mma_tf32(d, al, bh_);
    mma_tf32(d, ah, bl_);
}

// ---------------- top-k: exact bitonic sort of (sum,row) keys ----------------
__global__ void __launch_bounds__(1024) topk_kernel(
    const float* __restrict__ Q, const float* __restrict__ K,
    int* __restrict__ idxk, int* __restrict__ idxq)
{
    __shared__ unsigned long long keys[NN];
    int bh  = blockIdx.x >> 1;
    int isQ = blockIdx.x & 1;
    const float* src = isQ ? Q : K;
    int tid = threadIdx.x;

    for (int r = tid; r < NN; r += 1024) {
        const float4* p = reinterpret_cast<const float4*>(src + ((size_t)bh*NN + r)*DD);
        float s = 0.f;
#pragma unroll
        for (int t = 0; t < DD/4; t++) { float4 v = p[t]; s += v.x + v.y + v.z + v.w; }
        unsigned int u = __float_as_uint(s);
        unsigned int m = (u & 0x80000000u) ? ~u : (u | 0x80000000u);
        keys[r] = ((unsigned long long)(~m) << 32) | (unsigned int)r;
    }
    __syncthreads();

    for (int k = 2; k <= NN; k <<= 1) {
        for (int j = k >> 1; j > 0; j >>= 1) {
            for (int i = tid; i < NN; i += 1024) {
                int ixj = i ^ j;
                if (ixj > i) {
                    bool up = ((i & k) == 0);
                    unsigned long long a = keys[i], c = keys[ixj];
                    if ((a > c) == up) { keys[i] = c; keys[ixj] = a; }
                }
            }
            __syncthreads();
        }
    }
    int* dst = isQ ? idxq : idxk;
    if (tid < MM) dst[bh*MM + tid] = (int)(keys[tid] & 0xFFFFFFFFu);
}

// ---------------- gather nc = K[idx_k], nr = Q[idx_q]/8 ----------------
__global__ void gather_kernel(const float* __restrict__ Q, const float* __restrict__ K,
                              const int* __restrict__ idxk, const int* __restrict__ idxq,
                              float* __restrict__ nc, float* __restrict__ nr)
{
    int bh = blockIdx.x;
    int tx = threadIdx.x;
    int ty = threadIdx.y;
    for (int i = ty; i < MM; i += 4) {
        int ik = idxk[bh*MM + i];
        int iq = idxq[bh*MM + i];
        nc[((size_t)bh*MM + i)*DD + tx] = K[((size_t)bh*NN + ik)*DD + tx];
        nr[((size_t)bh*MM + i)*DD + tx] = Q[((size_t)bh*NN + iq)*DD + tx] * 0.125f;
    }
}

// ---------------- NT GEMM (K=64): 128x128 tile, 8x8 micro (fp32) -------------
__global__ void __launch_bounds__(256) gemm_nt128_kernel(
    const float* __restrict__ A, const float* __restrict__ B, float* __restrict__ C,
    int Ma, int Nb)
{
    extern __shared__ float sm[];
    float (*As)[132] = reinterpret_cast<float(*)[132]>(sm);
    float (*Bs)[132] = reinterpret_cast<float(*)[132]>(sm + 64*132);
    int bh = blockIdx.z;
    int m0 = blockIdx.y * 128;
    int n0 = blockIdx.x * 128;
    const float* Ab = A + (size_t)bh*Ma*64;
    const float* Bb = B + (size_t)bh*Nb*64;
    float*       Cb = C + (size_t)bh*Ma*Nb;
    int tid = threadIdx.x;
#pragma unroll
    for (int i = 0; i < 8; i++) {
        int idx = tid + i*256;
        int row = idx & 127;
        int c4  = (idx >> 7) * 4;
        float4 v = *reinterpret_cast<const float4*>(Ab + (size_t)(m0+row)*64 + c4);
        As[c4+0][row]=v.x; As[c4+1][row]=v.y; As[c4+2][row]=v.z; As[c4+3][row]=v.w;
        float4 w = *reinterpret_cast<const float4*>(Bb + (size_t)(n0+row)*64 + c4);
        Bs[c4+0][row]=w.x; Bs[c4+1][row]=w.y; Bs[c4+2][row]=w.z; Bs[c4+3][row]=w.w;
    }
    __syncthreads();
    int tx8 = (tid & 15) * 8, ty8 = (tid >> 4) * 8;
    float acc[8][8] = {};
#pragma unroll 8
    for (int kk = 0; kk < 64; kk++) {
        float a[8], b[8];
        *reinterpret_cast<float4*>(&a[0]) = *reinterpret_cast<float4*>(&As[kk][ty8]);
        *reinterpret_cast<float4*>(&a[4]) = *reinterpret_cast<float4*>(&As[kk][ty8+4]);
        *reinterpret_cast<float4*>(&b[0]) = *reinterpret_cast<float4*>(&Bs[kk][tx8]);
        *reinterpret_cast<float4*>(&b[4]) = *reinterpret_cast<float4*>(&Bs[kk][tx8+4]);
#pragma unroll
        for (int i = 0; i < 8; i++)
#pragma unroll
            for (int j = 0; j < 8; j++) acc[i][j] += a[i]*b[j];
    }
#pragma unroll
    for (int i = 0; i < 8; i++) {
        *reinterpret_cast<float4*>(Cb + (size_t)(m0+ty8+i)*Nb + n0+tx8) =
            make_float4(acc[i][0],acc[i][1],acc[i][2],acc[i][3]);
        *reinterpret_cast<float4*>(Cb + (size_t)(m0+ty8+i)*Nb + n0+tx8+4) =
            make_float4(acc[i][4],acc[i][5],acc[i][6],acc[i][7]);
    }
}

// ---------------- NT GEMM (K=64) in 3xTF32: C = (ascale*A) @ B^T -------------
// Tile 64m x 128n. grid (Nb/128, Ma/64, BH). Used for kernel_1 logits.
__global__ void __launch_bounds__(256) gemm_nt_x3_kernel(
    const float* __restrict__ A, const float* __restrict__ B, float* __restrict__ C,
    int Ma, int Nb, float ascale)
{
    extern __shared__ char smc[];
    uint2 (*As2)[68]  = reinterpret_cast<uint2(*)[68]> (smc);
    uint2 (*Bs2)[136] = reinterpret_cast<uint2(*)[136]>(smc + 64*68*8);
    int bh = blockIdx.z;
    int m0 = blockIdx.y * 64;
    int n0 = blockIdx.x * 128;
    const float* Ab = A + (size_t)bh*Ma*64;
    const float* Bb = B + (size_t)bh*Nb*64;
    float*       Cb = C + (size_t)bh*Ma*Nb;
    int tid = threadIdx.x, lane = tid & 31, wid = tid >> 5;
    int r4 = lane >> 2, c4 = lane & 3;
    int wm = (wid & 1) * 32;
    int wn = (wid >> 1) * 32;

#pragma unroll
    for (int i = 0; i < 4; i++) {
        int idx = tid + i*256;
        int m  = idx & 63;
        int kq = (idx >> 6) * 4;
        float4 v = *reinterpret_cast<const float4*>(Ab + (size_t)(m0+m)*64 + kq);
        As2[kq+0][m]=split_tf32(v.x*ascale); As2[kq+1][m]=split_tf32(v.y*ascale);
        As2[kq+2][m]=split_tf32(v.z*ascale); As2[kq+3][m]=split_tf32(v.w*ascale);
    }
#pragma unroll
    for (int i = 0; i < 8; i++) {
        int idx = tid + i*256;
        int n  = idx & 127;
        int kq = (idx >> 7) * 4;
        float4 v = *reinterpret_cast<const float4*>(Bb + (size_t)(n0+n)*64 + kq);
        Bs2[kq+0][n]=split_tf32(v.x); Bs2[kq+1][n]=split_tf32(v.y);
        Bs2[kq+2][n]=split_tf32(v.z); Bs2[kq+3][n]=split_tf32(v.w);
    }
    __syncthreads();

    float4 acc[2][4];
#pragma unroll
    for (int i = 0; i < 2; i++)
#pragma unroll
        for (int j = 0; j < 4; j++) acc[i][j] = make_float4(0.f,0.f,0.f,0.f);
#pragma unroll
    for (int ks = 0; ks < 8; ks++) {
        int k0 = ks*8;
        uint2 a2[2][4], b2[4][2];
#pragma unroll
        for (int i = 0; i < 2; i++) {
            int mb = wm + i*16;
            a2[i][0] = As2[k0+c4  ][mb+r4];
            a2[i][1] = As2[k0+c4  ][mb+8+r4];
            a2[i][2] = As2[k0+4+c4][mb+r4];
            a2[i][3] = As2[k0+4+c4][mb+8+r4];
        }
#pragma unroll
        for (int j = 0; j < 4; j++) {
            int nb = wn + j*8;
            b2[j][0] = Bs2[k0+c4  ][nb+r4];
            b2[j][1] = Bs2[k0+4+c4][nb+r4];
        }
#pragma unroll
        for (int i = 0; i < 2; i++)
#pragma unroll
            for (int j = 0; j < 4; j++) mma_tf32x3(acc[i][j], a2[i], b2[j]);
    }
#pragma unroll
    for (int i = 0; i < 2; i++) {
        int row0 = m0 + wm + i*16 + r4;
#pragma unroll
        for (int j = 0; j < 4; j++) {
            int col = n0 + wn + j*8 + 2*c4;
            *reinterpret_cast<float2*>(Cb + (size_t)row0*Nb + col) =
                make_float2(acc[i][j].x, acc[i][j].y);
            *reinterpret_cast<float2*>(Cb + (size_t)(row0+8)*Nb + col) =
                make_float2(acc[i][j].z, acc[i][j].w);
        }
    }
}

// ---------------- Newton split-K GEMM (single tf32; iterations 1..3) ---------
__global__ void __launch_bounds__(256) ns_tf32_kernel(
    const float* __restrict__ A, const float* __restrict__ B, float* __restrict__ P)
{
    __shared__ __align__(16) uint32_t As[32][136];
    __shared__ __align__(16) uint32_t Bs[32][136];
    int z  = blockIdx.z;
    int bh = z & (BH-1), s = z >> 4;
    int n0 = blockIdx.x * 128;
    int m0 = blockIdx.y * 128;
    const float* Ab = A + (size_t)bh*MM*MM;
    const float* Bb = B + (size_t)bh*MM*MM;
    int tid = threadIdx.x, lane = tid & 31, wid = tid >> 5;
    int wm = (wid & 1) * 64;
    int wn = (wid >> 1) * 32;
    int r4 = lane >> 2, c4 = lane & 3;
    float4 acc[4][4];
#pragma unroll
    for (int i = 0; i < 4; i++)
#pragma unroll
        for (int j = 0; j < 4; j++) acc[i][j] = make_float4(0.f,0.f,0.f,0.f);

    for (int kc = 0; kc < 4; kc++) {
        int k0g = s*128 + kc*32;
        if (kc) __syncthreads();
#pragma unroll
        for (int i = 0; i < 4; i++) {
            int idx = tid + i*256;
            int row = idx & 127;
            int kq  = (idx >> 7) * 4;
            float4 v = *reinterpret_cast<const float4*>(Ab + (size_t)(m0+row)*MM + k0g + kq);
            As[kq+0][row]=f2tf(v.x); As[kq+1][row]=f2tf(v.y);
            As[kq+2][row]=f2tf(v.z); As[kq+3][row]=f2tf(v.w);
        }
#pragma unroll
        for (int i = 0; i < 4; i++) {
            int idx = tid + i*256;
            int row = idx >> 5;
            int cq  = (idx & 31) * 4;
            float4 v = *reinterpret_cast<const float4*>(Bb + (size_t)(k0g+row)*MM + n0 + cq);
            uint4 t; t.x=f2tf(v.x); t.y=f2tf(v.y); t.z=f2tf(v.z); t.w=f2tf(v.w);
            *reinterpret_cast<uint4*>(&Bs[row][cq]) = t;
        }
        __syncthreads();
#pragma unroll
        for (int ks = 0; ks < 4; ks++) {
            int k0 = ks*8;
            uint32_t af[4][4], bf[4][2];
#pragma unroll
            for (int i = 0; i < 4; i++) {
                int mb = wm + i*16;
                af[i][0] = As[k0+c4  ][mb+r4];
                af[i][1] = As[k0+c4  ][mb+8+r4];
                af[i][2] = As[k0+4+c4][mb+r4];
                af[i][3] = As[k0+4+c4][mb+8+r4];
            }
#pragma unroll
            for (int j = 0; j < 4; j++) {
                int nb = wn + j*8;
                bf[j][0] = Bs[k0+c4  ][nb+r4];
                bf[j][1] = Bs[k0+4+c4][nb+r4];
            }
#pragma unroll
            for (int i = 0; i < 4; i++)
#pragma unroll
                for (int j = 0; j < 4; j++) mma_tf32(acc[i][j], af[i], bf[j]);
        }
    }
    float* Pb = P + (size_t)z*MM*MM;
#pragma unroll
    for (int i = 0; i < 4; i++) {
        int row0 = m0 + wm + i*16 + r4;
#pragma unroll
        for (int j = 0; j < 4; j++) {
            int col = n0 + wn + j*8 + c4*2;
            *reinterpret_cast<float2*>(Pb + (size_t)row0*MM + col) =
                make_float2(acc[i][j].x, acc[i][j].y);
            *reinterpret_cast<float2*>(Pb + (size_t)(row0+8)*MM + col) =
                make_float2(acc[i][j].z, acc[i][j].w);
        }
    }
}

// ---------------- Newton split-K GEMM (3xTF32, fp32-grade; iteration 4) ------
__global__ void __launch_bounds__(256) ns_tf32x3_kernel(
    const float* __restrict__ A, const float* __restrict__ B, float* __restrict__ P)
{
    extern __shared__ uint2 smu[];
    uint2 (*As2)[132] = reinterpret_cast<uint2(*)[132]>(smu);
    uint2 (*Bs2)[132] = reinterpret_cast<uint2(*)[132]>(smu + 32*132);
    int z  = blockIdx.z;
    int bh = z & (BH-1), s = z >> 4;
    int n0 = blockIdx.x * 128;
    int m0 = blockIdx.y * 128;
    const float* Ab = A + (size_t)bh*MM*MM;
    const float* Bb = B + (size_t)bh*MM*MM;
    int tid = threadIdx.x, lane = tid & 31, wid = tid >> 5;
    int wm = (wid & 1) * 64;
    int wn = (wid >> 1) * 32;
    int r4 = lane >> 2, c4 = lane & 3;
    float4 acc[4][4];
#pragma unroll
    for (int i = 0; i < 4; i++)
#pragma unroll
        for (int j = 0; j < 4; j++) acc[i][j] = make_float4(0.f,0.f,0.f,0.f);

    for (int kc = 0; kc < 4; kc++) {
        int k0g = s*128 + kc*32;
        if (kc) __syncthreads();
#pragma unroll
        for (int i = 0; i < 4; i++) {
            int idx = tid + i*256;
            int row = idx & 127;
            int kq  = (idx >> 7) * 4;
            float4 v = *reinterpret_cast<const float4*>(Ab + (size_t)(m0+row)*MM + k0g + kq);
            As2[kq+0][row]=split_tf32(v.x); As2[kq+1][row]=split_tf32(v.y);
            As2[kq+2][row]=split_tf32(v.z); As2[kq+3][row]=split_tf32(v.w);
        }
#pragma unroll
        for (int i = 0; i < 4; i++) {
            int idx = tid + i*256;
            int row = idx >> 5;
            int cq  = (idx & 31) * 4;
            float4 v = *reinterpret_cast<const float4*>(Bb + (size_t)(k0g+row)*MM + n0 + cq);
            Bs2[row][cq+0]=split_tf32(v.x); Bs2[row][cq+1]=split_tf32(v.y);
            Bs2[row][cq+2]=split_tf32(v.z); Bs2[row][cq+3]=split_tf32(v.w);
        }
        __syncthreads();
#pragma unroll
        for (int ks = 0; ks < 4; ks++) {
            int k0 = ks*8;
            uint2 a2[4][4], b2[4][2];
#pragma unroll
            for (int i = 0; i < 4; i++) {
                int mb = wm + i*16;
                a2[i][0] = As2[k0+c4  ][mb+r4];
                a2[i][1] = As2[k0+c4  ][mb+8+r4];
                a2[i][2] = As2[k0+4+c4][mb+r4];
                a2[i][3] = As2[k0+4+c4][mb+8+r4];
            }
#pragma unroll
            for (int j = 0; j < 4; j++) {
                int nb = wn + j*8;
                b2[j][0] = Bs2[k0+c4  ][nb+r4];
                b2[j][1] = Bs2[k0+4+c4][nb+r4];
            }
#pragma unroll
            for (int i = 0; i < 4; i++)
#pragma unroll
                for (int j = 0; j < 4; j++) mma_tf32x3(acc[i][j], a2[i], b2[j]);
        }
    }
    float* Pb = P + (size_t)z*MM*MM;
#pragma unroll
    for (int i = 0; i < 4; i++) {
        int row0 = m0 + wm + i*16 + r4;
#pragma unroll
        for (int j = 0; j < 4; j++) {
            int col = n0 + wn + j*8 + c4*2;
            *reinterpret_cast<float2*>(Pb + (size_t)row0*MM + col) =
                make_float2(acc[i][j].x, acc[i][j].y);
            *reinterpret_cast<float2*>(Pb + (size_t)(row0+8)*MM + col) =
                make_float2(acc[i][j].z, acc[i][j].w);
        }
    }
}

// Out = alpha*(P0+P1) + beta*Cadd
__global__ void ns_reduce_kernel(const float* __restrict__ P, const float* __restrict__ Cadd,
                                 float* __restrict__ Out, float alpha, float beta)
{
    size_t e = ((size_t)blockIdx.x * 256 + threadIdx.x) * 4;
    float4 p0 = *reinterpret_cast<const float4*>(P + e);
    float4 p1 = *reinterpret_cast<const float4*>(P + (size_t)BH*MM*MM + e);
    float4 v;
    v.x = alpha*(p0.x+p1.x); v.y = alpha*(p0.y+p1.y);
    v.z = alpha*(p0.z+p1.z); v.w = alpha*(p0.w+p1.w);
    if (Cadd) {
        float4 c = *reinterpret_cast<const float4*>(Cadd + e);
        v.x += beta*c.x; v.y += beta*c.y; v.z += beta*c.z; v.w += beta*c.w;
    }
    *reinterpret_cast<float4*>(Out + e) = v;
}

// ---------------- NN GEMM (small, for Y = inv @ RV) --------------------------
__global__ void __launch_bounds__(256) gemm_nn_kernel(
    const float* __restrict__ A, const float* __restrict__ B,
    float* __restrict__ Out, int Ma, int Nb, int Kd)
{
    __shared__ float As[64][65];
    __shared__ float Bs[64][65];
    int bh = blockIdx.z;
    int n0 = blockIdx.x * 64;
    int m0 = blockIdx.y * 64;
    const float* Ab = A + (size_t)bh*Ma*Kd;
    const float* Bb = B + (size_t)bh*Kd*Nb;
    float*       Ob = Out + (size_t)bh*Ma*Nb;
    int tid = threadIdx.x;
    int tx4 = (tid & 15) * 4, ty4 = (tid >> 4) * 4;
    float acc[4][4] = {};
    for (int k0 = 0; k0 < Kd; k0 += 64) {
        for (int l = tid; l < 64*16; l += 256) {
            int row = l >> 4, c4 = (l & 15) * 4;
            float4 va = *reinterpret_cast<const float4*>(Ab + (size_t)(m0+row)*Kd + k0 + c4);
            As[row][c4+0]=va.x; As[row][c4+1]=va.y; As[row][c4+2]=va.z; As[row][c4+3]=va.w;
            float4 vb = *reinterpret_cast<const float4*>(Bb + (size_t)(k0+row)*Nb + n0 + c4);
            Bs[row][c4+0]=vb.x; Bs[row][c4+1]=vb.y; Bs[row][c4+2]=vb.z; Bs[row][c4+3]=vb.w;
        }
        __syncthreads();
#pragma unroll 16
        for (int kk = 0; kk < 64; kk++) {
            float a0=As[ty4+0][kk], a1=As[ty4+1][kk], a2=As[ty4+2][kk], a3=As[ty4+3][kk];
            float b0=Bs[kk][tx4+0], b1=Bs[kk][tx4+1], b2=Bs[kk][tx4+2], b3=Bs[kk][tx4+3];
            acc[0][0]+=a0*b0; acc[0][1]+=a0*b1; acc[0][2]+=a0*b2; acc[0][3]+=a0*b3;
            acc[1][0]+=a1*b0; acc[1][1]+=a1*b1; acc[1][2]+=a1*b2; acc[1][3]+=a1*b3;
            acc[2][0]+=a2*b0; acc[2][1]+=a2*b1; acc[2][2]+=a2*b2; acc[2][3]+=a2*b3;
            acc[3][0]+=a3*b0; acc[3][1]+=a3*b1; acc[3][2]+=a3*b2; acc[3][3]+=a3*b3;
        }
        __syncthreads();
    }
#pragma unroll
    for (int i = 0; i < 4; i++) {
        size_t off = (size_t)(m0+ty4+i)*Nb + n0 + tx4;
        *reinterpret_cast<float4*>(Ob + off) =
            make_float4(acc[i][0], acc[i][1], acc[i][2], acc[i][3]);
    }
}

// ---------------- row softmax (in place), one block per row ------------------
__global__ void softmax_rows_kernel(float* __restrict__ data, int cols)
{
    extern __shared__ float buf[];
    __shared__ float red[256];
    size_t row = blockIdx.x;
    float* d = data + row * (size_t)cols;
    int tid = threadIdx.x;
    float mx = -FLT_MAX;
    for (int c = tid; c < cols; c += 256) { float v = d[c]; buf[c] = v; mx = fmaxf(mx, v); }
    red[tid] = mx; __syncthreads();
    for (int st = 128; st > 0; st >>= 1) { if (tid < st) red[tid] = fmaxf(red[tid], red[tid+st]); __syncthreads(); }
    mx = red[0];
    __syncthreads();
    float s = 0.f;
    for (int c = tid; c < cols; c += 256) { float e = __expf(buf[c] - mx); buf[c] = e; s += e; }
    red[tid] = s; __syncthreads();
    for (int st = 128; st > 0; st >>= 1) { if (tid < st) red[tid] += red[tid+st]; __syncthreads(); }
    float inv = 1.0f / red[0];
    for (int c = tid; c < cols; c += 256) d[c] = buf[c] * inv;
}

// ---------------- V0 = u^T / max_j(colsum_j(u)) ------------------------------
__global__ void __launch_bounds__(256) v0init_kernel(const float* __restrict__ U, float* __restrict__ V0)
{
    __shared__ float red[256];
    int bh = blockIdx.x;
    const float* u = U  + (size_t)bh*MM*MM;
    float*       v = V0 + (size_t)bh*MM*MM;
    int j = threadIdx.x;
    float s = 0.f;
    for (int i = 0; i < MM; i++) s += u[(size_t)i*MM + j];
    red[j] = s; __syncthreads();
    for (int st = 128; st > 0; st >>= 1) { if (j < st) red[j] = fmaxf(red[j], red[j+st]); __syncthreads(); }
    float scale = 1.0f / red[0];
    for (int q = 0; q < MM; q++) v[(size_t)j*MM + q] = scale * u[(size_t)q*MM + j];
}

// ---------------- RV split-K partials: 128x64 tile, 8x4 micro (fp32) ---------
__global__ void __launch_bounds__(256) rv_partial_kernel(
    const float* __restrict__ R, const float* __restrict__ Vv, float* __restrict__ P)
{
    extern __shared__ float sm[];
    float (*Rs)[68] = reinterpret_cast<float(*)[68]>(sm);
    float (*Vs)[68] = reinterpret_cast<float(*)[68]>(sm + 128*68);
    int s  = blockIdx.x;
    int m0 = blockIdx.y * 128;
    int bh = blockIdx.z;
    const float* Rb = R  + (size_t)bh*MM*NN;
    const float* Vb = Vv + (size_t)bh*NN*DD;
    int tid = threadIdx.x;
    int ry = (tid >> 4) * 8;
    int cx = (tid & 15) * 4;
    float acc[8][4] = {};
    for (int kc = 0; kc < 8; kc++) {
        int k0 = s*512 + kc*64;
        __syncthreads();
#pragma unroll
        for (int i = 0; i < 8; i++) {
            int idx = tid + i*256;
            int row = idx >> 4, c4 = (idx & 15) * 4;
            *reinterpret_cast<float4*>(&Rs[row][c4]) =
                *reinterpret_cast<const float4*>(Rb + (size_t)(m0+row)*NN + k0 + c4);
        }
#pragma unroll
        for (int i = 0; i < 4; i++) {
            int idx = tid + i*256;
            int row = idx >> 4, c4 = (idx & 15) * 4;
            *reinterpret_cast<float4*>(&Vs[row][c4]) =
                *reinterpret_cast<const float4*>(Vb + (size_t)(k0+row)*DD + c4);
        }
        __syncthreads();
#pragma unroll 8
        for (int kk = 0; kk < 64; kk++) {
            float b[4];
            *reinterpret_cast<float4*>(&b[0]) = *reinterpret_cast<float4*>(&Vs[kk][cx]);
            float a[8];
#pragma unroll
            for (int i = 0; i < 8; i++) a[i] = Rs[ry+i][kk];
#pragma unroll
            for (int i = 0; i < 8; i++)
#pragma unroll
                for (int j = 0; j < 4; j++) acc[i][j] += a[i]*b[j];
        }
    }
    float* Pb = P + ((size_t)s*BH + bh)*MM*DD;
#pragma unroll
    for (int i = 0; i < 8; i++)
        *reinterpret_cast<float4*>(Pb + (size_t)(m0+ry+i)*DD + cx) =
            make_float4(acc[i][0], acc[i][1], acc[i][2], acc[i][3]);
}

__global__ void rv_reduce_kernel(const float* __restrict__ P, float* __restrict__ RV)
{
    int e = blockIdx.x * 256 + threadIdx.x;
    float s = 0.f;
#pragma unroll
    for (int t = 0; t < 8; t++) s += P[(size_t)t*BH*MM*DD + e];
    RV[e] = s;
}

// ---------------- final: X = kernel_1 @ Y  (fp32, 128x64 tile, K=256) --------
__global__ void __launch_bounds__(256) xgemm_kernel(
    const float* __restrict__ P, const float* __restrict__ Yy, float* __restrict__ X)
{
    extern __shared__ float sm[];
    float (*Ps)[68] = reinterpret_cast<float(*)[68]>(sm);
    float (*Ys)[68] = reinterpret_cast<float(*)[68]>(sm + 128*68);
    int m0 = blockIdx.y * 128;
    int bh = blockIdx.z;
    const float* Pb = P  + (size_t)bh*NN*MM;
    const float* Yb = Yy + (size_t)bh*MM*DD;
    int tid = threadIdx.x;
    int ry = (tid >> 4) * 8;
    int cx = (tid & 15) * 4;
    float acc[8][4] = {};
    for (int kc = 0; kc < 4; kc++) {
        int k0 = kc*64;
        if (kc) __syncthreads();
#pragma unroll
        for (int i = 0; i < 8; i++) {
            int idx = tid + i*256;
            int row = idx >> 4, c4 = (idx & 15) * 4;
            *reinterpret_cast<float4*>(&Ps[row][c4]) =
                *reinterpret_cast<const float4*>(Pb + (size_t)(m0+row)*MM + k0 + c4);
        }
#pragma unroll
        for (int i = 0; i < 4; i++) {
            int idx = tid + i*256;
            int row = idx >> 4, c4 = (idx & 15) * 4;
            *reinterpret_cast<float4*>(&Ys[row][c4]) =
                *reinterpret_cast<const float4*>(Yb + (size_t)(k0+row)*DD + c4);
        }
        __syncthreads();
#pragma unroll 8
        for (int kk = 0; kk < 64; kk++) {
            float b[4];
            *reinterpret_cast<float4*>(&b[0]) = *reinterpret_cast<float4*>(&Ys[kk][cx]);
            float a[8];
#pragma unroll
            for (int i = 0; i < 8; i++) a[i] = Ps[ry+i][kk];
#pragma unroll
            for (int i = 0; i < 8; i++)
#pragma unroll
                for (int j = 0; j < 4; j++) acc[i][j] += a[i]*b[j];
        }
    }
#pragma unroll
    for (int i = 0; i < 8; i++)
        *reinterpret_cast<float4*>(X + ((size_t)bh*NN + m0 + ry + i)*DD + cx) =
            make_float4(acc[i][0], acc[i][1], acc[i][2], acc[i][3]);
}

// ---------------- host launch ----------------
extern "C" void kernel_launch(void* const* d_in, const int* in_sizes, int n_in,
                              void* d_out, int out_size)
{
    (void)in_sizes; (void)n_in; (void)out_size;
    const float* Q = (const float*)d_in[0];
    const float* K = (const float*)d_in[1];
    const float* V = (const float*)d_in[2];
    float* X = (float*)d_out;

    static cudaStream_t s2 = nullptr, s3 = nullptr;
    static cudaEvent_t evFork = nullptr, evJoin2 = nullptr, evJoin3 = nullptr;
    static bool attrs_done = false;
    if (!s2) {
        cudaStreamCreateWithFlags(&s2, cudaStreamNonBlocking);
        cudaStreamCreateWithFlags(&s3, cudaStreamNonBlocking);
        cudaEventCreateWithFlags(&evFork,  cudaEventDisableTiming);
        cudaEventCreateWithFlags(&evJoin2, cudaEventDisableTiming);
        cudaEventCreateWithFlags(&evJoin3, cudaEventDisableTiming);
    }
    const int NT_SMEM   = 2*64*132*sizeof(float);        // fp32 NT GEMM
    const int NTX3_SMEM = 64*68*8 + 64*136*8;            // 3xTF32 NT GEMM (kernel_1)
    const int NS3_SMEM  = 2*32*132*sizeof(uint2);        // ns_tf32x3
    const int RV_SMEM   = (128*68 + 64*68)*sizeof(float);
    const int XG_SMEM   = (128*68 + 64*68)*sizeof(float);
    if (!attrs_done) {
        cudaFuncSetAttribute(gemm_nt128_kernel, cudaFuncAttributeMaxDynamicSharedMemorySize, NT_SMEM);
        cudaFuncSetAttribute(gemm_nt_x3_kernel, cudaFuncAttributeMaxDynamicSharedMemorySize, NTX3_SMEM);
        cudaFuncSetAttribute(ns_tf32x3_kernel,  cudaFuncAttributeMaxDynamicSharedMemorySize, NS3_SMEM);
        cudaFuncSetAttribute(rv_partial_kernel, cudaFuncAttributeMaxDynamicSharedMemorySize, RV_SMEM);
        cudaFuncSetAttribute(xgemm_kernel,      cudaFuncAttributeMaxDynamicSharedMemorySize, XG_SMEM);
        attrs_done = true;
    }

    float *nc, *nr, *u, *v0, *v1, *kv, *t1, *t2, *nsp, *r, *p, *rvp, *rv, *y;
    int *ik, *iq;
    cudaGetSymbolAddress((void**)&nc, g_nc);
    cudaGetSymbolAddress((void**)&nr, g_nr);
    cudaGetSymbolAddress((void**)&ik, g_idxk);
    cudaGetSymbolAddress((void**)&iq, g_idxq);
    cudaGetSymbolAddress((void**)&u,  g_u);
    cudaGetSymbolAddress((void**)&v0, g_v0);
    cudaGetSymbolAddress((void**)&v1, g_v1);
    cudaGetSymbolAddress((void**)&kv, g_kv);
    cudaGetSymbolAddress((void**)&t1, g_t1);
    cudaGetSymbolAddress((void**)&t2, g_t2);
    cudaGetSymbolAddress((void**)&nsp, g_nsp);
    cudaGetSymbolAddress((void**)&r,  g_r);
    cudaGetSymbolAddress((void**)&p,  g_p);
    cudaGetSymbolAddress((void**)&rvp, g_rvp);
    cudaGetSymbolAddress((void**)&rv, g_rv);
    cudaGetSymbolAddress((void**)&y,  g_y);

    // 1) selection + gather
    topk_kernel<<<32, 1024>>>(Q, K, ik, iq);
    gather_kernel<<<16, dim3(64,4)>>>(Q, K, ik, iq, nc, nr);

    cudaEventRecord(evFork, 0);
    cudaStreamWaitEvent(s2, evFork, 0);
    cudaStreamWaitEvent(s3, evFork, 0);

    // s2 (FMA pipe): kernel_3 = softmax(nr @ K^T) fp32; RV = kernel_3 @ V fp32
    gemm_nt128_kernel<<<dim3(NN/128, 2, 16), 256, NT_SMEM, s2>>>(nr, K, r, MM, NN);
    softmax_rows_kernel<<<BH*MM, 256, NN*sizeof(float), s2>>>(r, NN);
    rv_partial_kernel<<<dim3(8, 2, 16), 256, RV_SMEM, s2>>>(r, V, rvp);
    rv_reduce_kernel<<<BH*MM*DD/256, 256, 0, s2>>>(rvp, rv);
    cudaEventRecord(evJoin2, s2);

    // s3 (tensor pipe): kernel_1 = softmax(Qs @ nc^T), 3xTF32 logits
    gemm_nt_x3_kernel<<<dim3(MM/128, NN/64, 16), 256, NTX3_SMEM, s3>>>(Q, nc, p, NN, MM, 0.125f);
    softmax_rows_kernel<<<(size_t)BH*NN, 256, MM*sizeof(float), s3>>>(p, MM);
    cudaEventRecord(evJoin3, s3);

    // main (tensor pipe): u = softmax(nr @ nc^T); Newton-Schulz inverse
    gemm_nt128_kernel<<<dim3(2, 2, 16), 256, NT_SMEM>>>(nr, nc, u, MM, MM);
    softmax_rows_kernel<<<BH*MM, 256, MM*sizeof(float)>>>(u, MM);
    v0init_kernel<<<16, 256>>>(u, v0);

    const int RB = BH*MM*MM/1024;
    float* vin = v0; float* vout = v1;
    for (int it = 0; it < 4; it++) {
        bool x3 = (it == 3);   // final iteration fp32-grade (3xTF32, tensor pipe)
        if (x3) ns_tf32x3_kernel<<<dim3(2,2,2*BH), 256, NS3_SMEM>>>(u, vin, nsp);
        else    ns_tf32_kernel  <<<dim3(2,2,2*BH), 256>>>(u, vin, nsp);
        ns_reduce_kernel<<<RB, 256>>>(nsp, nullptr, kv,  1.0f,  0.0f);
        if (x3) ns_tf32x3_kernel<<<dim3(2,2,2*BH), 256, NS3_SMEM>>>(kv, kv, nsp);
        else    ns_tf32_kernel  <<<dim3(2,2,2*BH), 256>>>(kv, kv, nsp);
        ns_reduce_kernel<<<RB, 256>>>(nsp, kv,      t1, -1.0f,  7.0f);
        if (x3) ns_tf32x3_kernel<<<dim3(2,2,2*BH), 256, NS3_SMEM>>>(kv, t1, nsp);
        else    ns_tf32_kernel  <<<dim3(2,2,2*BH), 256>>>(kv, t1, nsp);
        ns_reduce_kernel<<<RB, 256>>>(nsp, kv,      t2, -1.0f, 15.0f);
        if (x3) ns_tf32x3_kernel<<<dim3(2,2,2*BH), 256, NS3_SMEM>>>(vin, t2, nsp);
        else    ns_tf32_kernel  <<<dim3(2,2,2*BH), 256>>>(vin, t2, nsp);
        ns_reduce_kernel<<<RB, 256>>>(nsp, vin,     vout, -0.25f, 3.25f);
        float* tmp = vin; vin = vout; vout = tmp;
    }

    // join rv, then Y = V_inv @ RV
    cudaStreamWaitEvent(0, evJoin2, 0);
    gemm_nn_kernel<<<dim3(1,4,16), 256>>>(vin, rv, y, MM, DD, MM);

    // join kernel_1, then X = kernel_1 @ Y (fp32 tail)
    cudaStreamWaitEvent(0, evJoin3, 0);
    xgemm_kernel<<<dim3(1, NN/128, 16), 256, XG_SMEM>>>(p, y, X);
}

// round 10
// speedup vs baseline: 1.1316x; 1.1316x over previous
#include <cuda_runtime.h>
#include <float.h>
#include <stdint.h>

#define BH 16
#define HH 8
#define NN 4096
#define DD 64
#define MM 256

// ---------------- scratch (__device__ globals; no allocation) ----------------
__device__ float g_nc [BH*MM*DD];
__device__ float g_nr [BH*MM*DD];
__device__ int   g_idxk[BH*MM];
__device__ int   g_idxq[BH*MM];
__device__ float g_u  [BH*MM*MM];
__device__ float g_v0 [BH*MM*MM];
__device__ float g_v1 [BH*MM*MM];
__device__ float g_kv [BH*MM*MM];
__device__ float g_t1 [BH*MM*MM];
__device__ float g_t2 [BH*MM*MM];
__device__ float g_r  [(size_t)BH*MM*NN];   // 64 MB: kernel_3
__device__ float g_rvp[8*BH*MM*DD];
__device__ float g_rv [BH*MM*DD];
__device__ float g_y  [BH*MM*DD];
__device__ unsigned g_bar;                   // persistent-NS grid barrier

// ---------------- tf32 mma helpers ----------------
__device__ __forceinline__ uint32_t f2tf(float v) {
    uint32_t r; asm("cvt.rna.tf32.f32 %0, %1;" : "=r"(r) : "f"(v)); return r;
}
__device__ __forceinline__ void mma_tf32(float4& d, const uint32_t* a, const uint32_t* b) {
    asm volatile("mma.sync.aligned.m16n8k8.row.col.f32.tf32.tf32.f32 "
        "{%0,%1,%2,%3}, {%4,%5,%6,%7}, {%8,%9}, {%0,%1,%2,%3};"
        : "+f"(d.x), "+f"(d.y), "+f"(d.z), "+f"(d.w)
        : "r"(a[0]), "r"(a[1]), "r"(a[2]), "r"(a[3]), "r"(b[0]), "r"(b[1]));
}

// ---------------- top-k: exact bitonic sort of (sum,row) keys ----------------
__global__ void __launch_bounds__(1024) topk_kernel(
    const float* __restrict__ Q, const float* __restrict__ K,
    int* __restrict__ idxk, int* __restrict__ idxq)
{
    __shared__ unsigned long long keys[NN];
    int bh  = blockIdx.x >> 1;
    int isQ = blockIdx.x & 1;
    const float* src = isQ ? Q : K;
    int tid = threadIdx.x;

    for (int r = tid; r < NN; r += 1024) {
        const float4* p = reinterpret_cast<const float4*>(src + ((size_t)bh*NN + r)*DD);
        float s = 0.f;
#pragma unroll
        for (int t = 0; t < DD/4; t++) { float4 v = p[t]; s += v.x + v.y + v.z + v.w; }
        unsigned int u = __float_as_uint(s);
        unsigned int m = (u & 0x80000000u) ? ~u : (u | 0x80000000u);
        keys[r] = ((unsigned long long)(~m) << 32) | (unsigned int)r;
    }
    __syncthreads();

    for (int k = 2; k <= NN; k <<= 1) {
        for (int j = k >> 1; j > 0; j >>= 1) {
            for (int i = tid; i < NN; i += 1024) {
                int ixj = i ^ j;
                if (ixj > i) {
                    bool up = ((i & k) == 0);
                    unsigned long long a = keys[i], c = keys[ixj];
                    if ((a > c) == up) { keys[i] = c; keys[ixj] = a; }
                }
            }
            __syncthreads();
        }
    }
    int* dst = isQ ? idxq : idxk;
    if (tid < MM) dst[bh*MM + tid] = (int)(keys[tid] & 0xFFFFFFFFu);
}

// ---------------- gather nc = K[idx_k], nr = Q[idx_q]/8 ----------------
__global__ void gather_kernel(const float* __restrict__ Q, const float* __restrict__ K,
                              const int* __restrict__ idxk, const int* __restrict__ idxq,
                              float* __restrict__ nc, float* __restrict__ nr)
{
    int bh = blockIdx.x;
    int tx = threadIdx.x;
    int ty = threadIdx.y;
    for (int i = ty; i < MM; i += 4) {
        int ik = idxk[bh*MM + i];
        int iq = idxq[bh*MM + i];
        nc[((size_t)bh*MM + i)*DD + tx] = K[((size_t)bh*NN + ik)*DD + tx];
        nr[((size_t)bh*MM + i)*DD + tx] = Q[((size_t)bh*NN + iq)*DD + tx] * 0.125f;
    }
}

// ---------------- NT GEMM (K=64): 128x128 tile, 8x8 micro (fp32) -------------
__global__ void __launch_bounds__(256) gemm_nt128_kernel(
    const float* __restrict__ A, const float* __restrict__ B, float* __restrict__ C,
    int Ma, int Nb)
{
    extern __shared__ float sm[];
    float (*As)[132] = reinterpret_cast<float(*)[132]>(sm);
    float (*Bs)[132] = reinterpret_cast<float(*)[132]>(sm + 64*132);
    int bh = blockIdx.z;
    int m0 = blockIdx.y * 128;
    int n0 = blockIdx.x * 128;
    const float* Ab = A + (size_t)bh*Ma*64;
    const float* Bb = B + (size_t)bh*Nb*64;
    float*       Cb = C + (size_t)bh*Ma*Nb;
    int tid = threadIdx.x;
#pragma unroll
    for (int i = 0; i < 8; i++) {
        int idx = tid + i*256;
        int row = idx & 127;
        int c4  = (idx >> 7) * 4;
        float4 v = *reinterpret_cast<const float4*>(Ab + (size_t)(m0+row)*64 + c4);
        As[c4+0][row]=v.x; As[c4+1][row]=v.y; As[c4+2][row]=v.z; As[c4+3][row]=v.w;
        float4 w = *reinterpret_cast<const float4*>(Bb + (size_t)(n0+row)*64 + c4);
        Bs[c4+0][row]=w.x; Bs[c4+1][row]=w.y; Bs[c4+2][row]=w.z; Bs[c4+3][row]=w.w;
    }
    __syncthreads();
    int tx8 = (tid & 15) * 8, ty8 = (tid >> 4) * 8;
    float acc[8][8] = {};
#pragma unroll 8
    for (int kk = 0; kk < 64; kk++) {
        float a[8], b[8];
        *reinterpret_cast<float4*>(&a[0]) = *reinterpret_cast<float4*>(&As[kk][ty8]);
        *reinterpret_cast<float4*>(&a[4]) = *reinterpret_cast<float4*>(&As[kk][ty8+4]);
        *reinterpret_cast<float4*>(&b[0]) = *reinterpret_cast<float4*>(&Bs[kk][tx8]);
        *reinterpret_cast<float4*>(&b[4]) = *reinterpret_cast<float4*>(&Bs[kk][tx8+4]);
#pragma unroll
        for (int i = 0; i < 8; i++)
#pragma unroll
            for (int j = 0; j < 8; j++) acc[i][j] += a[i]*b[j];
    }
#pragma unroll
    for (int i = 0; i < 8; i++) {
        *reinterpret_cast<float4*>(Cb + (size_t)(m0+ty8+i)*Nb + n0+tx8) =
            make_float4(acc[i][0],acc[i][1],acc[i][2],acc[i][3]);
        *reinterpret_cast<float4*>(Cb + (size_t)(m0+ty8+i)*Nb + n0+tx8+4) =
            make_float4(acc[i][4],acc[i][5],acc[i][6],acc[i][7]);
    }
}

// ---------------- persistent Newton-Schulz chain -----------------------------
// One kernel runs all 16 GEMM steps with software grid barriers between them.
// 128 blocks (8 tiles of 128m x 64n per bh x 16 bh) -- all co-resident.
__global__ void zero_bar_kernel() { g_bar = 0u; }

__device__ __forceinline__ void grid_bar(unsigned target) {
    __syncthreads();
    if (threadIdx.x == 0) {
        __threadfence();                       // release: make our writes visible
        atomicAdd(&g_bar, 1u);
        volatile unsigned* vb = &g_bar;
        while (*vb < target) {}
    }
    __syncthreads();
    __threadfence();                           // gpu-scope fence: invalidates L1D,
                                               // so reads below see peer blocks' writes
}

// single-tf32 step (iterations 1..3; Newton-Schulz self-corrects the noise).
// 64x32 warp tiles, warp-split-K (kg in {0,1}), smem k-reduction + epilogue.
__device__ __noinline__ void ns_step_tf32(
    const float* __restrict__ Ab, const float* __restrict__ Bb,
    const float* __restrict__ Cb, float* __restrict__ Ob,
    float alpha, float beta, int m0, int n0, char* smc)
{
    uint32_t (*As)[136] = reinterpret_cast<uint32_t(*)[136]>(smc);            // [64k][136m]
    uint32_t (*Bs)[72]  = reinterpret_cast<uint32_t(*)[72]> (smc + 64*136*4); // [64k][72n]
    int tid = threadIdx.x, lane = tid & 31, wid = tid >> 5;
    int r4 = lane >> 2, c4 = lane & 3;
    int wm = (wid & 1) * 64;
    int wn = ((wid >> 1) & 1) * 32;
    int kg = wid >> 2;
    int kb = kg * 32;

    float4 acc[4][4];
#pragma unroll
    for (int i = 0; i < 4; i++)
#pragma unroll
        for (int j = 0; j < 4; j++) acc[i][j] = make_float4(0.f,0.f,0.f,0.f);

    for (int sc = 0; sc < 4; sc++) {
        int k0g = sc * 64;
        if (sc) __syncthreads();
#pragma unroll
        for (int i = 0; i < 8; i++) {            // A: 128m x 64k
            int idx = tid + i*256;
            int row = idx & 127;
            int kq  = (idx >> 7) * 4;
            float4 v = *reinterpret_cast<const float4*>(Ab + (size_t)(m0+row)*MM + k0g + kq);
            As[kq+0][row]=f2tf(v.x); As[kq+1][row]=f2tf(v.y);
            As[kq+2][row]=f2tf(v.z); As[kq+3][row]=f2tf(v.w);
        }
#pragma unroll
        for (int i = 0; i < 4; i++) {            // B: 64k x 64n
            int idx = tid + i*256;
            int row = idx >> 4;
            int cq  = (idx & 15) * 4;
            float4 v = *reinterpret_cast<const float4*>(Bb + (size_t)(k0g+row)*MM + n0 + cq);
            Bs[row][cq+0]=f2tf(v.x); Bs[row][cq+1]=f2tf(v.y);
            Bs[row][cq+2]=f2tf(v.z); Bs[row][cq+3]=f2tf(v.w);
        }
        __syncthreads();
#pragma unroll
        for (int ks = 0; ks < 4; ks++) {
            int k0 = kb + ks*8;
            uint32_t af[4][4], bf[4][2];
#pragma unroll
            for (int i = 0; i < 4; i++) {
                int mb = wm + i*16;
                af[i][0] = As[k0+c4  ][mb+r4];
                af[i][1] = As[k0+c4  ][mb+8+r4];
                af[i][2] = As[k0+4+c4][mb+r4];
                af[i][3] = As[k0+4+c4][mb+8+r4];
            }
#pragma unroll
            for (int j = 0; j < 4; j++) {
                int nb = wn + j*8;
                bf[j][0] = Bs[k0+c4  ][nb+r4];
                bf[j][1] = Bs[k0+4+c4][nb+r4];
            }
#pragma unroll
            for (int i = 0; i < 4; i++)
#pragma unroll
                for (int j = 0; j < 4; j++) mma_tf32(acc[i][j], af[i], bf[j]);
        }
    }

    // intra-block k-reduction: kg1 warps stash, kg0 warps add + epilogue
    __syncthreads();
    float4* red = reinterpret_cast<float4*>(smc);   // 32 KB, overlays As
    if (kg == 1) {
        int slot = wid - 4;
#pragma unroll
        for (int f = 0; f < 16; f++)
            red[((size_t)f*4 + slot)*32 + lane] = acc[f>>2][f&3];
    }
    __syncthreads();
    if (kg == 0) {
#pragma unroll
        for (int f = 0; f < 16; f++) {
            float4 o = red[((size_t)f*4 + wid)*32 + lane];
            acc[f>>2][f&3].x += o.x; acc[f>>2][f&3].y += o.y;
            acc[f>>2][f&3].z += o.z; acc[f>>2][f&3].w += o.w;
        }
#pragma unroll
        for (int i = 0; i < 4; i++) {
            int row0 = m0 + wm + i*16 + r4;
#pragma unroll
            for (int j = 0; j < 4; j++) {
                int col = n0 + wn + j*8 + 2*c4;
                float2 v0 = make_float2(alpha*acc[i][j].x, alpha*acc[i][j].y);
                float2 v1 = make_float2(alpha*acc[i][j].z, alpha*acc[i][j].w);
                if (Cb) {
                    float2 c0 = *reinterpret_cast<const float2*>(Cb + (size_t)row0*MM + col);
                    float2 c1 = *reinterpret_cast<const float2*>(Cb + (size_t)(row0+8)*MM + col);
                    v0.x += beta*c0.x; v0.y += beta*c0.y;
                    v1.x += beta*c1.x; v1.y += beta*c1.y;
                }
                *reinterpret_cast<float2*>(Ob + (size_t)row0*MM + col) = v0;
                *reinterpret_cast<float2*>(Ob + (size_t)(row0+8)*MM + col) = v1;
            }
        }
    }
}

// fp32 step (final iteration -- its noise reaches the output). 8x4 micro.
__device__ __noinline__ void ns_step_fp32(
    const float* __restrict__ Ab, const float* __restrict__ Bb,
    const float* __restrict__ Cb, float* __restrict__ Ob,
    float alpha, float beta, int m0, int n0, char* smc)
{
    float (*Asf)[68] = reinterpret_cast<float(*)[68]>(smc);                   // [128m][68k]
    float (*Bsf)[68] = reinterpret_cast<float(*)[68]>(reinterpret_cast<float*>(smc) + 128*68); // [64k][68n]
    int tid = threadIdx.x;
    int ry = (tid >> 4) * 8;
    int cx = (tid & 15) * 4;
    float acc[8][4] = {};
    for (int kc = 0; kc < 4; kc++) {
        int k0 = kc*64;
        if (kc) __syncthreads();
#pragma unroll
        for (int i = 0; i < 8; i++) {
            int idx = tid + i*256;
            int row = idx >> 4, q4 = (idx & 15) * 4;
            *reinterpret_cast<float4*>(&Asf[row][q4]) =
                *reinterpret_cast<const float4*>(Ab + (size_t)(m0+row)*MM + k0 + q4);
        }
#pragma unroll
        for (int i = 0; i < 4; i++) {
            int idx = tid + i*256;
            int row = idx >> 4, q4 = (idx & 15) * 4;
            *reinterpret_cast<float4*>(&Bsf[row][q4]) =
                *reinterpret_cast<const float4*>(Bb + (size_t)(k0+row)*MM + n0 + q4);
        }
        __syncthreads();
#pragma unroll 8
        for (int kk = 0; kk < 64; kk++) {
            float b[4];
            *reinterpret_cast<float4*>(&b[0]) = *reinterpret_cast<float4*>(&Bsf[kk][cx]);
            float a[8];
#pragma unroll
            for (int i = 0; i < 8; i++) a[i] = Asf[ry+i][kk];
#pragma unroll
            for (int i = 0; i < 8; i++)
#pragma unroll
                for (int j = 0; j < 4; j++) acc[i][j] += a[i]*b[j];
        }
    }
#pragma unroll
    for (int i = 0; i < 8; i++) {
        size_t off = (size_t)(m0+ry+i)*MM + n0 + cx;
        float4 v = make_float4(alpha*acc[i][0], alpha*acc[i][1],
                               alpha*acc[i][2], alpha*acc[i][3]);
        if (Cb) {
            float4 c = *reinterpret_cast<const float4*>(Cb + off);
            v.x += beta*c.x; v.y += beta*c.y; v.z += beta*c.z; v.w += beta*c.w;
        }
        *reinterpret_cast<float4*>(Ob + off) = v;
    }
}

__global__ void __launch_bounds__(256) ns_persist_kernel(
    const float* __restrict__ u, float* __restrict__ v0, float* __restrict__ v1,
    float* __restrict__ kv, float* __restrict__ t1, float* __restrict__ t2)
{
    extern __shared__ char smc[];
    int bx   = blockIdx.x;          // 0..127
    int bh   = bx >> 3;
    int tile = bx & 7;
    int m0 = (tile & 1) * 128;
    int n0 = (tile >> 1) * 64;
    size_t off = (size_t)bh*MM*MM;
    const float* ub = u + off;
    float* kvb = kv + off;
    float* t1b = t1 + off;
    float* t2b = t2 + off;
    float* vinb  = v0 + off;
    float* voutb = v1 + off;

    unsigned tgt = 0;
    for (int it = 0; it < 4; it++) {
        bool f32 = (it == 3);
        if (f32) ns_step_fp32(ub, vinb, nullptr, kvb, 1.0f, 0.0f, m0, n0, smc);
        else     ns_step_tf32(ub, vinb, nullptr, kvb, 1.0f, 0.0f, m0, n0, smc);
        tgt += 128; grid_bar(tgt);
        if (f32) ns_step_fp32(kvb, kvb, kvb, t1b, -1.0f, 7.0f, m0, n0, smc);
        else     ns_step_tf32(kvb, kvb, kvb, t1b, -1.0f, 7.0f, m0, n0, smc);
        tgt += 128; grid_bar(tgt);
        if (f32) ns_step_fp32(kvb, t1b, kvb, t2b, -1.0f, 15.0f, m0, n0, smc);
        else     ns_step_tf32(kvb, t1b, kvb, t2b, -1.0f, 15.0f, m0, n0, smc);
        tgt += 128; grid_bar(tgt);
        if (f32) ns_step_fp32(vinb, t2b, vinb, voutb, -0.25f, 3.25f, m0, n0, smc);
        else     ns_step_tf32(vinb, t2b, vinb, voutb, -0.25f, 3.25f, m0, n0, smc);
        if (it < 3) { tgt += 128; grid_bar(tgt); }
        float* tmp = vinb; vinb = voutb; voutb = tmp;
    }
    // final inverse lands in v0 (4 swaps)
}

// ---------------- NN GEMM (small, for Y = inv @ RV) --------------------------
__global__ void __launch_bounds__(256) gemm_nn_kernel(
    const float* __restrict__ A, const float* __restrict__ B,
    float* __restrict__ Out, int Ma, int Nb, int Kd)
{
    __shared__ float As[64][65];
    __shared__ float Bs[64][65];
    int bh = blockIdx.z;
    int n0 = blockIdx.x * 64;
    int m0 = blockIdx.y * 64;
    const float* Ab = A + (size_t)bh*Ma*Kd;
    const float* Bb = B + (size_t)bh*Kd*Nb;
    float*       Ob = Out + (size_t)bh*Ma*Nb;
    int tid = threadIdx.x;
    int tx4 = (tid & 15) * 4, ty4 = (tid >> 4) * 4;
    float acc[4][4] = {};
    for (int k0 = 0; k0 < Kd; k0 += 64) {
        for (int l = tid; l < 64*16; l += 256) {
            int row = l >> 4, c4 = (l & 15) * 4;
            float4 va = *reinterpret_cast<const float4*>(Ab + (size_t)(m0+row)*Kd + k0 + c4);
            As[row][c4+0]=va.x; As[row][c4+1]=va.y; As[row][c4+2]=va.z; As[row][c4+3]=va.w;
            float4 vb = *reinterpret_cast<const float4*>(Bb + (size_t)(k0+row)*Nb + n0 + c4);
            Bs[row][c4+0]=vb.x; Bs[row][c4+1]=vb.y; Bs[row][c4+2]=vb.z; Bs[row][c4+3]=vb.w;
        }
        __syncthreads();
#pragma unroll 16
        for (int kk = 0; kk < 64; kk++) {
            float a0=As[ty4+0][kk], a1=As[ty4+1][kk], a2=As[ty4+2][kk], a3=As[ty4+3][kk];
            float b0=Bs[kk][tx4+0], b1=Bs[kk][tx4+1], b2=Bs[kk][tx4+2], b3=Bs[kk][tx4+3];
            acc[0][0]+=a0*b0; acc[0][1]+=a0*b1; acc[0][2]+=a0*b2; acc[0][3]+=a0*b3;
            acc[1][0]+=a1*b0; acc[1][1]+=a1*b1; acc[1][2]+=a1*b2; acc[1][3]+=a1*b3;
            acc[2][0]+=a2*b0; acc[2][1]+=a2*b1; acc[2][2]+=a2*b2; acc[2][3]+=a2*b3;
            acc[3][0]+=a3*b0; acc[3][1]+=a3*b1; acc[3][2]+=a3*b2; acc[3][3]+=a3*b3;
        }
        __syncthreads();
    }
#pragma unroll
    for (int i = 0; i < 4; i++) {
        size_t off = (size_t)(m0+ty4+i)*Nb + n0 + tx4;
        *reinterpret_cast<float4*>(Ob + off) =
            make_float4(acc[i][0], acc[i][1], acc[i][2], acc[i][3]);
    }
}

// ---------------- row softmax (in place), one block per row ------------------
__global__ void softmax_rows_kernel(float* __restrict__ data, int cols)
{
    extern __shared__ float buf[];
    __shared__ float red[256];
    size_t row = blockIdx.x;
    float* d = data + row * (size_t)cols;
    int tid = threadIdx.x;
    float mx = -FLT_MAX;
    for (int c = tid; c < cols; c += 256) { float v = d[c]; buf[c] = v; mx = fmaxf(mx, v); }
    red[tid] = mx; __syncthreads();
    for (int st = 128; st > 0; st >>= 1) { if (tid < st) red[tid] = fmaxf(red[tid], red[tid+st]); __syncthreads(); }
    mx = red[0];
    __syncthreads();
    float s = 0.f;
    for (int c = tid; c < cols; c += 256) { float e = __expf(buf[c] - mx); buf[c] = e; s += e; }
    red[tid] = s; __syncthreads();
    for (int st = 128; st > 0; st >>= 1) { if (tid < st) red[tid] += red[tid+st]; __syncthreads(); }
    float inv = 1.0f / red[0];
    for (int c = tid; c < cols; c += 256) d[c] = buf[c] * inv;
}

// ---------------- V0 = u^T / max_j(colsum_j(u)) ------------------------------
__global__ void __launch_bounds__(256) v0init_kernel(const float* __restrict__ U, float* __restrict__ V0)
{
    __shared__ float red[256];
    int bh = blockIdx.x;
    const float* u = U  + (size_t)bh*MM*MM;
    float*       v = V0 + (size_t)bh*MM*MM;
    int j = threadIdx.x;
    float s = 0.f;
    for (int i = 0; i < MM; i++) s += u[(size_t)i*MM + j];
    red[j] = s; __syncthreads();
    for (int st = 128; st > 0; st >>= 1) { if (j < st) red[j] = fmaxf(red[j], red[j+st]); __syncthreads(); }
    float scale = 1.0f / red[0];
    for (int q = 0; q < MM; q++) v[(size_t)j*MM + q] = scale * u[(size_t)q*MM + j];
}

// ---------------- RV split-K partials: 128x64 tile, 8x4 micro (fp32) ---------
__global__ void __launch_bounds__(256) rv_partial_kernel(
    const float* __restrict__ R, const float* __restrict__ Vv, float* __restrict__ P)
{
    extern __shared__ float sm[];
    float (*Rs)[68] = reinterpret_cast<float(*)[68]>(sm);
    float (*Vs)[68] = reinterpret_cast<float(*)[68]>(sm + 128*68);
    int s  = blockIdx.x;
    int m0 = blockIdx.y * 128;
    int bh = blockIdx.z;
    const float* Rb = R  + (size_t)bh*MM*NN;
    const float* Vb = Vv + (size_t)bh*NN*DD;
    int tid = threadIdx.x;
    int ry = (tid >> 4) * 8;
    int cx = (tid & 15) * 4;
    float acc[8][4] = {};
    for (int kc = 0; kc < 8; kc++) {
        int k0 = s*512 + kc*64;
        __syncthreads();
#pragma unroll
        for (int i = 0; i < 8; i++) {
            int idx = tid + i*256;
            int row = idx >> 4, c4 = (idx & 15) * 4;
            *reinterpret_cast<float4*>(&Rs[row][c4]) =
                *reinterpret_cast<const float4*>(Rb + (size_t)(m0+row)*NN + k0 + c4);
        }
#pragma unroll
        for (int i = 0; i < 4; i++) {
            int idx = tid + i*256;
            int row = idx >> 4, c4 = (idx & 15) * 4;
            *reinterpret_cast<float4*>(&Vs[row][c4]) =
                *reinterpret_cast<const float4*>(Vb + (size_t)(k0+row)*DD + c4);
        }
        __syncthreads();
#pragma unroll 8
        for (int kk = 0; kk < 64; kk++) {
            float b[4];
            *reinterpret_cast<float4*>(&b[0]) = *reinterpret_cast<float4*>(&Vs[kk][cx]);
            float a[8];
#pragma unroll
            for (int i = 0; i < 8; i++) a[i] = Rs[ry+i][kk];
#pragma unroll
            for (int i = 0; i < 8; i++)
#pragma unroll
                for (int j = 0; j < 4; j++) acc[i][j] += a[i]*b[j];
        }
    }
    float* Pb = P + ((size_t)s*BH + bh)*MM*DD;
#pragma unroll
    for (int i = 0; i < 8; i++)
        *reinterpret_cast<float4*>(Pb + (size_t)(m0+ry+i)*DD + cx) =
            make_float4(acc[i][0], acc[i][1], acc[i][2], acc[i][3]);
}

__global__ void rv_reduce_kernel(const float* __restrict__ P, float* __restrict__ RV)
{
    int e = blockIdx.x * 256 + threadIdx.x;
    float s = 0.f;
#pragma unroll
    for (int t = 0; t < 8; t++) s += P[(size_t)t*BH*MM*DD + e];
    RV[e] = s;
}

// ---------------- fused final: X_chunk = softmax(Qs_chunk @ nc^T) @ Y --------
#define FX_LPAD 260
__global__ void __launch_bounds__(256) fusedx_kernel(
    const float* __restrict__ Q, const float* __restrict__ nc,
    const float* __restrict__ Y, float* __restrict__ X)
{
    extern __shared__ float sm[];
    float (*As)[132] = reinterpret_cast<float(*)[132]>(sm);
    float (*Bs)[132] = reinterpret_cast<float(*)[132]>(sm + 64*132);
    float (*Ys)[68]  = reinterpret_cast<float(*)[68]> (sm + 64*132);
    float (*L)[FX_LPAD] = reinterpret_cast<float(*)[FX_LPAD]>(sm + 2*64*132);
    int bh = blockIdx.y;
    int q0 = blockIdx.x * 128;
    int tid = threadIdx.x;
    const float* Qb  = Q  + (size_t)bh*NN*DD;
    const float* ncb = nc + (size_t)bh*MM*DD;
    const float* Yb  = Y  + (size_t)bh*MM*DD;

#pragma unroll
    for (int i = 0; i < 8; i++) {
        int idx = tid + i*256;
        int row = idx & 127;
        int c4  = (idx >> 7) * 4;
        float4 v = *reinterpret_cast<const float4*>(Qb + (size_t)(q0+row)*DD + c4);
        As[c4+0][row]=v.x*0.125f; As[c4+1][row]=v.y*0.125f;
        As[c4+2][row]=v.z*0.125f; As[c4+3][row]=v.w*0.125f;
    }

    int tx8 = (tid & 15) * 8, ty8 = (tid >> 4) * 8;
    for (int cc = 0; cc < 2; cc++) {
        __syncthreads();
#pragma unroll
        for (int i = 0; i < 8; i++) {
            int idx = tid + i*256;
            int row = idx & 127;
            int c4  = (idx >> 7) * 4;
            float4 v = *reinterpret_cast<const float4*>(ncb + (size_t)(cc*128+row)*DD + c4);
            Bs[c4+0][row]=v.x; Bs[c4+1][row]=v.y; Bs[c4+2][row]=v.z; Bs[c4+3][row]=v.w;
        }
        __syncthreads();
        float acc[8][8] = {};
#pragma unroll 8
        for (int kk = 0; kk < 64; kk++) {
            float a[8], b[8];
            *reinterpret_cast<float4*>(&a[0]) = *reinterpret_cast<float4*>(&As[kk][ty8]);
            *reinterpret_cast<float4*>(&a[4]) = *reinterpret_cast<float4*>(&As[kk][ty8+4]);
            *reinterpret_cast<float4*>(&b[0]) = *reinterpret_cast<float4*>(&Bs[kk][tx8]);
            *reinterpret_cast<float4*>(&b[4]) = *reinterpret_cast<float4*>(&Bs[kk][tx8+4]);
#pragma unroll
            for (int i = 0; i < 8; i++)
#pragma unroll
                for (int j = 0; j < 8; j++) acc[i][j] += a[i]*b[j];
        }
#pragma unroll
        for (int i = 0; i < 8; i++) {
            *reinterpret_cast<float4*>(&L[ty8+i][cc*128+tx8]) =
                make_float4(acc[i][0],acc[i][1],acc[i][2],acc[i][3]);
            *reinterpret_cast<float4*>(&L[ty8+i][cc*128+tx8+4]) =
                make_float4(acc[i][4],acc[i][5],acc[i][6],acc[i][7]);
        }
    }
    __syncthreads();

    int wid = tid >> 5, lane = tid & 31;
    for (int r = wid; r < 128; r += 8) {
        float v[8]; float mx = -FLT_MAX;
#pragma unroll
        for (int t = 0; t < 8; t++) { v[t] = L[r][lane + 32*t]; mx = fmaxf(mx, v[t]); }
#pragma unroll
        for (int o = 16; o > 0; o >>= 1) mx = fmaxf(mx, __shfl_xor_sync(0xffffffffu, mx, o));
        float s = 0.f;
#pragma unroll
        for (int t = 0; t < 8; t++) { v[t] = __expf(v[t] - mx); s += v[t]; }
#pragma unroll
        for (int o = 16; o > 0; o >>= 1) s += __shfl_xor_sync(0xffffffffu, s, o);
        float inv = 1.0f / s;
#pragma unroll
        for (int t = 0; t < 8; t++) L[r][lane + 32*t] = v[t] * inv;
    }

    int ry = (tid >> 4) * 8;
    int cx = (tid & 15) * 4;
    float acc3[8][4] = {};
    for (int kc = 0; kc < 4; kc++) {
        __syncthreads();
#pragma unroll
        for (int i = 0; i < 4; i++) {
            int idx = tid + i*256;
            int row = idx >> 4, c4 = (idx & 15) * 4;
            *reinterpret_cast<float4*>(&Ys[row][c4]) =
                *reinterpret_cast<const float4*>(Yb + (size_t)(kc*64+row)*DD + c4);
        }
        __syncthreads();
#pragma unroll 8
        for (int kk = 0; kk < 64; kk++) {
            float b[4];
            *reinterpret_cast<float4*>(&b[0]) = *reinterpret_cast<float4*>(&Ys[kk][cx]);
            float a[8];
#pragma unroll
            for (int i = 0; i < 8; i++) a[i] = L[ry+i][kc*64+kk];
#pragma unroll
            for (int i = 0; i < 8; i++)
#pragma unroll
                for (int j = 0; j < 4; j++) acc3[i][j] += a[i]*b[j];
        }
    }
#pragma unroll
    for (int i = 0; i < 8; i++)
        *reinterpret_cast<float4*>(X + ((size_t)bh*NN + q0 + ry + i)*DD + cx) =
            make_float4(acc3[i][0], acc3[i][1], acc3[i][2], acc3[i][3]);
}

// ---------------- host launch ----------------
extern "C" void kernel_launch(void* const* d_in, const int* in_sizes, int n_in,
                              void* d_out, int out_size)
{
    (void)in_sizes; (void)n_in; (void)out_size;
    const float* Q = (const float*)d_in[0];
    const float* K = (const float*)d_in[1];
    const float* V = (const float*)d_in[2];
    float* X = (float*)d_out;

    static cudaStream_t s2 = nullptr;
    static cudaEvent_t evFork = nullptr, evJoin = nullptr;
    static bool attrs_done = false;
    if (!s2) {
        cudaStreamCreateWithFlags(&s2, cudaStreamNonBlocking);
        cudaEventCreateWithFlags(&evFork, cudaEventDisableTiming);
        cudaEventCreateWithFlags(&evJoin, cudaEventDisableTiming);
    }
    const int NT_SMEM  = 2*64*132*sizeof(float);               // 67.5 KB
    const int RV_SMEM  = (128*68 + 64*68)*sizeof(float);       // 52.2 KB
    const int NSP_SMEM = 64*136*4 + 64*72*4;                   // 53.2 KB
    const int FX_SMEM  = (2*64*132 + 128*FX_LPAD)*sizeof(float); // 200.7 KB
    if (!attrs_done) {
        cudaFuncSetAttribute(gemm_nt128_kernel, cudaFuncAttributeMaxDynamicSharedMemorySize, NT_SMEM);
        cudaFuncSetAttribute(rv_partial_kernel, cudaFuncAttributeMaxDynamicSharedMemorySize, RV_SMEM);
        cudaFuncSetAttribute(ns_persist_kernel, cudaFuncAttributeMaxDynamicSharedMemorySize, NSP_SMEM);
        cudaFuncSetAttribute(fusedx_kernel,     cudaFuncAttributeMaxDynamicSharedMemorySize, FX_SMEM);
        attrs_done = true;
    }

    float *nc, *nr, *u, *v0, *v1, *kv, *t1, *t2, *r, *rvp, *rv, *y;
    int *ik, *iq;
    cudaGetSymbolAddress((void**)&nc, g_nc);
    cudaGetSymbolAddress((void**)&nr, g_nr);
    cudaGetSymbolAddress((void**)&ik, g_idxk);
    cudaGetSymbolAddress((void**)&iq, g_idxq);
    cudaGetSymbolAddress((void**)&u,  g_u);
    cudaGetSymbolAddress((void**)&v0, g_v0);
    cudaGetSymbolAddress((void**)&v1, g_v1);
    cudaGetSymbolAddress((void**)&kv, g_kv);
    cudaGetSymbolAddress((void**)&t1, g_t1);
    cudaGetSymbolAddress((void**)&t2, g_t2);
    cudaGetSymbolAddress((void**)&r,  g_r);
    cudaGetSymbolAddress((void**)&rvp, g_rvp);
    cudaGetSymbolAddress((void**)&rv, g_rv);
    cudaGetSymbolAddress((void**)&y,  g_y);

    // 1) selection + gather
    topk_kernel<<<32, 1024>>>(Q, K, ik, iq);
    gather_kernel<<<16, dim3(64,4)>>>(Q, K, ik, iq, nc, nr);

    // fork: r-pipeline (fp32, FMA pipe) overlaps main-stream tensor work
    cudaEventRecord(evFork, 0);
    cudaStreamWaitEvent(s2, evFork, 0);

    gemm_nt128_kernel<<<dim3(NN/128, 2, 16), 256, NT_SMEM, s2>>>(nr, K, r, MM, NN);
    softmax_rows_kernel<<<BH*MM, 256, NN*sizeof(float), s2>>>(r, NN);
    rv_partial_kernel<<<dim3(8, 2, 16), 256, RV_SMEM, s2>>>(r, V, rvp);
    rv_reduce_kernel<<<BH*MM*DD/256, 256, 0, s2>>>(rvp, rv);
    cudaEventRecord(evJoin, s2);

    // main: u = softmax(nr @ nc^T); Newton-Schulz inverse (ONE persistent kernel)
    gemm_nt128_kernel<<<dim3(2, 2, 16), 256, NT_SMEM>>>(nr, nc, u, MM, MM);
    softmax_rows_kernel<<<BH*MM, 256, MM*sizeof(float)>>>(u, MM);
    v0init_kernel<<<16, 256>>>(u, v0);
    zero_bar_kernel<<<1, 1>>>();
    ns_persist_kernel<<<128, 256, NSP_SMEM>>>(u, v0, v1, kv, t1, t2);
    // final inverse in v0

    // join: need rv before Y
    cudaStreamWaitEvent(0, evJoin, 0);

    // 7) Y = V_inv @ RV
    gemm_nn_kernel<<<dim3(1,4,16), 256>>>(v0, rv, y, MM, DD, MM);
    // 8) X = softmax(Qs @ nc^T) @ Y, fused per 128-row chunk
    fusedx_kernel<<<dim3(NN/128, BH), 256, FX_SMEM>>>(Q, nc, y, X);
}

// round 11
// speedup vs baseline: 1.1767x; 1.0399x over previous
#include <cuda_runtime.h>
#include <float.h>
#include <stdint.h>

#define BH 16
#define HH 8
#define NN 4096
#define DD 64
#define MM 256

// ---------------- scratch (__device__ globals; no allocation) ----------------
__device__ float g_nc [BH*MM*DD];
__device__ float g_nr [BH*MM*DD];
__device__ int   g_idxk[BH*MM];
__device__ int   g_idxq[BH*MM];
__device__ float g_u  [BH*MM*MM];
__device__ float g_v0 [BH*MM*MM];
__device__ float g_v1 [BH*MM*MM];
__device__ float g_kv [BH*MM*MM];
__device__ float g_t1 [BH*MM*MM];
__device__ float g_t2 [BH*MM*MM];
__device__ float g_nsp[2*BH*MM*MM];          // split-K partials (iteration 4)
__device__ float g_r  [(size_t)BH*MM*NN];    // 64 MB: kernel_3
__device__ float g_rvp[8*BH*MM*DD];
__device__ float g_rv [BH*MM*DD];
__device__ float g_y  [BH*MM*DD];

// ---------------- tf32 mma helpers ----------------
__device__ __forceinline__ uint32_t f2tf(float v) {
    uint32_t r; asm("cvt.rna.tf32.f32 %0, %1;" : "=r"(r) : "f"(v)); return r;
}
__device__ __forceinline__ void mma_tf32(float4& d, const uint32_t* a, const uint32_t* b) {
    asm volatile("mma.sync.aligned.m16n8k8.row.col.f32.tf32.tf32.f32 "
        "{%0,%1,%2,%3}, {%4,%5,%6,%7}, {%8,%9}, {%0,%1,%2,%3};"
        : "+f"(d.x), "+f"(d.y), "+f"(d.z), "+f"(d.w)
        : "r"(a[0]), "r"(a[1]), "r"(a[2]), "r"(a[3]), "r"(b[0]), "r"(b[1]));
}
__device__ __forceinline__ uint2 split_tf32(float x) {
    uint32_t hi = f2tf(x);
    float lo = x - __uint_as_float(hi);
    return make_uint2(hi, f2tf(lo));
}
// 3xTF32: d += a_hi*b_hi + a_lo*b_hi + a_hi*b_lo (fp32-grade)
__device__ __forceinline__ void mma_tf32x3(float4& d, const uint2* a, const uint2* b) {
    uint32_t ah[4] = {a[0].x, a[1].x, a[2].x, a[3].x};
    uint32_t al[4] = {a[0].y, a[1].y, a[2].y, a[3].y};
    uint32_t bh_[2] = {b[0].x, b[1].x};
    uint32_t bl_[2] = {b[0].y, b[1].y};
    mma_tf32(d, ah, bh_);
    mma_tf32(d, al, bh_);
    mma_tf32(d, ah, bl_);
}

// ---------------- top-k: exact bitonic sort of (sum,row) keys ----------------
__global__ void __launch_bounds__(1024) topk_kernel(
    const float* __restrict__ Q, const float* __restrict__ K,
    int* __restrict__ idxk, int* __restrict__ idxq)
{
    __shared__ unsigned long long keys[NN];
    int bh  = blockIdx.x >> 1;
    int isQ = blockIdx.x & 1;
    const float* src = isQ ? Q : K;
    int tid = threadIdx.x;

    for (int r = tid; r < NN; r += 1024) {
        const float4* p = reinterpret_cast<const float4*>(src + ((size_t)bh*NN + r)*DD);
        float s = 0.f;
#pragma unroll
        for (int t = 0; t < DD/4; t++) { float4 v = p[t]; s += v.x + v.y + v.z + v.w; }
        unsigned int u = __float_as_uint(s);
        unsigned int m = (u & 0x80000000u) ? ~u : (u | 0x80000000u);
        keys[r] = ((unsigned long long)(~m) << 32) | (unsigned int)r;
    }
    __syncthreads();

    for (int k = 2; k <= NN; k <<= 1) {
        for (int j = k >> 1; j > 0; j >>= 1) {
            for (int i = tid; i < NN; i += 1024) {
                int ixj = i ^ j;
                if (ixj > i) {
                    bool up = ((i & k) == 0);
                    unsigned long long a = keys[i], c = keys[ixj];
                    if ((a > c) == up) { keys[i] = c; keys[ixj] = a; }
                }
            }
            __syncthreads();
        }
    }
    int* dst = isQ ? idxq : idxk;
    if (tid < MM) dst[bh*MM + tid] = (int)(keys[tid] & 0xFFFFFFFFu);
}

// ---------------- gather nc = K[idx_k], nr = Q[idx_q]/8 ----------------
__global__ void gather_kernel(const float* __restrict__ Q, const float* __restrict__ K,
                              const int* __restrict__ idxk, const int* __restrict__ idxq,
                              float* __restrict__ nc, float* __restrict__ nr)
{
    int bh = blockIdx.x;
    int tx = threadIdx.x;
    int ty = threadIdx.y;
    for (int i = ty; i < MM; i += 4) {
        int ik = idxk[bh*MM + i];
        int iq = idxq[bh*MM + i];
        nc[((size_t)bh*MM + i)*DD + tx] = K[((size_t)bh*NN + ik)*DD + tx];
        nr[((size_t)bh*MM + i)*DD + tx] = Q[((size_t)bh*NN + iq)*DD + tx] * 0.125f;
    }
}

// ---------------- NT GEMM (K=64): 128x128 tile, 8x8 micro (fp32) -------------
__global__ void __launch_bounds__(256) gemm_nt128_kernel(
    const float* __restrict__ A, const float* __restrict__ B, float* __restrict__ C,
    int Ma, int Nb)
{
    extern __shared__ float sm[];
    float (*As)[132] = reinterpret_cast<float(*)[132]>(sm);
    float (*Bs)[132] = reinterpret_cast<float(*)[132]>(sm + 64*132);
    int bh = blockIdx.z;
    int m0 = blockIdx.y * 128;
    int n0 = blockIdx.x * 128;
    const float* Ab = A + (size_t)bh*Ma*64;
    const float* Bb = B + (size_t)bh*Nb*64;
    float*       Cb = C + (size_t)bh*Ma*Nb;
    int tid = threadIdx.x;
#pragma unroll
    for (int i = 0; i < 8; i++) {
        int idx = tid + i*256;
        int row = idx & 127;
        int c4  = (idx >> 7) * 4;
        float4 v = *reinterpret_cast<const float4*>(Ab + (size_t)(m0+row)*64 + c4);
        As[c4+0][row]=v.x; As[c4+1][row]=v.y; As[c4+2][row]=v.z; As[c4+3][row]=v.w;
        float4 w = *reinterpret_cast<const float4*>(Bb + (size_t)(n0+row)*64 + c4);
        Bs[c4+0][row]=w.x; Bs[c4+1][row]=w.y; Bs[c4+2][row]=w.z; Bs[c4+3][row]=w.w;
    }
    __syncthreads();
    int tx8 = (tid & 15) * 8, ty8 = (tid >> 4) * 8;
    float acc[8][8] = {};
#pragma unroll 8
    for (int kk = 0; kk < 64; kk++) {
        float a[8], b[8];
        *reinterpret_cast<float4*>(&a[0]) = *reinterpret_cast<float4*>(&As[kk][ty8]);
        *reinterpret_cast<float4*>(&a[4]) = *reinterpret_cast<float4*>(&As[kk][ty8+4]);
        *reinterpret_cast<float4*>(&b[0]) = *reinterpret_cast<float4*>(&Bs[kk][tx8]);
        *reinterpret_cast<float4*>(&b[4]) = *reinterpret_cast<float4*>(&Bs[kk][tx8+4]);
#pragma unroll
        for (int i = 0; i < 8; i++)
#pragma unroll
            for (int j = 0; j < 8; j++) acc[i][j] += a[i]*b[j];
    }
#pragma unroll
    for (int i = 0; i < 8; i++) {
        *reinterpret_cast<float4*>(Cb + (size_t)(m0+ty8+i)*Nb + n0+tx8) =
            make_float4(acc[i][0],acc[i][1],acc[i][2],acc[i][3]);
        *reinterpret_cast<float4*>(Cb + (size_t)(m0+ty8+i)*Nb + n0+tx8+4) =
            make_float4(acc[i][4],acc[i][5],acc[i][6],acc[i][7]);
    }
}

// ---------------- NS fused GEMM (single tf32, full K, fused epilogue) --------
// Out = alpha*(A@B) + beta*Cadd. Tile 128m x 64n, K=256 (4 chunks of 64).
// 8 warps: 2m x 2n x 2k-split; 64x32 warp tiles; smem k-reduction.
// grid (4, 2, 16). Proven correct in R8/R10.
__global__ void __launch_bounds__(256) ns_fused1_kernel(
    const float* __restrict__ A, const float* __restrict__ B,
    const float* __restrict__ Cadd, float* __restrict__ Out,
    float alpha, float beta)
{
    extern __shared__ char smc[];
    uint32_t (*As)[136] = reinterpret_cast<uint32_t(*)[136]>(smc);            // [64k][136m]
    uint32_t (*Bs)[72]  = reinterpret_cast<uint32_t(*)[72]> (smc + 64*136*4); // [64k][72n]
    int bh = blockIdx.z;
    int n0 = blockIdx.x * 64;
    int m0 = blockIdx.y * 128;
    const float* Ab = A + (size_t)bh*MM*MM;
    const float* Bb = B + (size_t)bh*MM*MM;
    float*       Ob = Out + (size_t)bh*MM*MM;
    int tid = threadIdx.x, lane = tid & 31, wid = tid >> 5;
    int r4 = lane >> 2, c4 = lane & 3;
    int wm = (wid & 1) * 64;
    int wn = ((wid >> 1) & 1) * 32;
    int kg = wid >> 2;
    int kb = kg * 32;

    float4 acc[4][4];
#pragma unroll
    for (int i = 0; i < 4; i++)
#pragma unroll
        for (int j = 0; j < 4; j++) acc[i][j] = make_float4(0.f,0.f,0.f,0.f);

    for (int sc = 0; sc < 4; sc++) {
        int k0g = sc * 64;
        if (sc) __syncthreads();
#pragma unroll
        for (int i = 0; i < 8; i++) {            // A: 128m x 64k
            int idx = tid + i*256;
            int row = idx & 127;
            int kq  = (idx >> 7) * 4;
            float4 v = *reinterpret_cast<const float4*>(Ab + (size_t)(m0+row)*MM + k0g + kq);
            As[kq+0][row]=f2tf(v.x); As[kq+1][row]=f2tf(v.y);
            As[kq+2][row]=f2tf(v.z); As[kq+3][row]=f2tf(v.w);
        }
#pragma unroll
        for (int i = 0; i < 4; i++) {            // B: 64k x 64n
            int idx = tid + i*256;
            int row = idx >> 4;
            int cq  = (idx & 15) * 4;
            float4 v = *reinterpret_cast<const float4*>(Bb + (size_t)(k0g+row)*MM + n0 + cq);
            Bs[row][cq+0]=f2tf(v.x); Bs[row][cq+1]=f2tf(v.y);
            Bs[row][cq+2]=f2tf(v.z); Bs[row][cq+3]=f2tf(v.w);
        }
        __syncthreads();
#pragma unroll
        for (int ks = 0; ks < 4; ks++) {
            int k0 = kb + ks*8;
            uint32_t af[4][4], bf[4][2];
#pragma unroll
            for (int i = 0; i < 4; i++) {
                int mb = wm + i*16;
                af[i][0] = As[k0+c4  ][mb+r4];
                af[i][1] = As[k0+c4  ][mb+8+r4];
                af[i][2] = As[k0+4+c4][mb+r4];
                af[i][3] = As[k0+4+c4][mb+8+r4];
            }
#pragma unroll
            for (int j = 0; j < 4; j++) {
                int nb = wn + j*8;
                bf[j][0] = Bs[k0+c4  ][nb+r4];
                bf[j][1] = Bs[k0+4+c4][nb+r4];
            }
#pragma unroll
            for (int i = 0; i < 4; i++)
#pragma unroll
                for (int j = 0; j < 4; j++) mma_tf32(acc[i][j], af[i], bf[j]);
        }
    }

    // intra-block k-reduction: kg1 warps stash, kg0 warps add + epilogue
    __syncthreads();
    float4* red = reinterpret_cast<float4*>(smc);
    if (kg == 1) {
        int slot = wid - 4;
#pragma unroll
        for (int f = 0; f < 16; f++)
            red[((size_t)f*4 + slot)*32 + lane] = acc[f>>2][f&3];
    }
    __syncthreads();
    if (kg == 0) {
        const float* Cb = Cadd ? (Cadd + (size_t)bh*MM*MM) : nullptr;
#pragma unroll
        for (int f = 0; f < 16; f++) {
            float4 o = red[((size_t)f*4 + wid)*32 + lane];
            acc[f>>2][f&3].x += o.x; acc[f>>2][f&3].y += o.y;
            acc[f>>2][f&3].z += o.z; acc[f>>2][f&3].w += o.w;
        }
#pragma unroll
        for (int i = 0; i < 4; i++) {
            int row0 = m0 + wm + i*16 + r4;
#pragma unroll
            for (int j = 0; j < 4; j++) {
                int col = n0 + wn + j*8 + 2*c4;
                float2 v0 = make_float2(alpha*acc[i][j].x, alpha*acc[i][j].y);
                float2 v1 = make_float2(alpha*acc[i][j].z, alpha*acc[i][j].w);
                if (Cb) {
                    float2 c0 = *reinterpret_cast<const float2*>(Cb + (size_t)row0*MM + col);
                    float2 c1 = *reinterpret_cast<const float2*>(Cb + (size_t)(row0+8)*MM + col);
                    v0.x += beta*c0.x; v0.y += beta*c0.y;
                    v1.x += beta*c1.x; v1.y += beta*c1.y;
                }
                *reinterpret_cast<float2*>(Ob + (size_t)row0*MM + col) = v0;
                *reinterpret_cast<float2*>(Ob + (size_t)(row0+8)*MM + col) = v1;
            }
        }
    }
}

// ---------------- Newton split-K GEMM (3xTF32, fp32-grade; iteration 4) ------
// grid (2, 2, 2*BH). Proven correct in R6/R9.
__global__ void __launch_bounds__(256) ns_tf32x3_kernel(
    const float* __restrict__ A, const float* __restrict__ B, float* __restrict__ P)
{
    extern __shared__ uint2 smu[];
    uint2 (*As2)[132] = reinterpret_cast<uint2(*)[132]>(smu);
    uint2 (*Bs2)[132] = reinterpret_cast<uint2(*)[132]>(smu + 32*132);
    int z  = blockIdx.z;
    int bh = z & (BH-1), s = z >> 4;
    int n0 = blockIdx.x * 128;
    int m0 = blockIdx.y * 128;
    const float* Ab = A + (size_t)bh*MM*MM;
    const float* Bb = B + (size_t)bh*MM*MM;
    int tid = threadIdx.x, lane = tid & 31, wid = tid >> 5;
    int wm = (wid & 1) * 64;
    int wn = (wid >> 1) * 32;
    int r4 = lane >> 2, c4 = lane & 3;
    float4 acc[4][4];
#pragma unroll
    for (int i = 0; i < 4; i++)
#pragma unroll
        for (int j = 0; j < 4; j++) acc[i][j] = make_float4(0.f,0.f,0.f,0.f);

    for (int kc = 0; kc < 4; kc++) {
        int k0g = s*128 + kc*32;
        if (kc) __syncthreads();
#pragma unroll
        for (int i = 0; i < 4; i++) {
            int idx = tid + i*256;
            int row = idx & 127;
            int kq  = (idx >> 7) * 4;
            float4 v = *reinterpret_cast<const float4*>(Ab + (size_t)(m0+row)*MM + k0g + kq);
            As2[kq+0][row]=split_tf32(v.x); As2[kq+1][row]=split_tf32(v.y);
            As2[kq+2][row]=split_tf32(v.z); As2[kq+3][row]=split_tf32(v.w);
        }
#pragma unroll
        for (int i = 0; i < 4; i++) {
            int idx = tid + i*256;
            int row = idx >> 5;
            int cq  = (idx & 31) * 4;
            float4 v = *reinterpret_cast<const float4*>(Bb + (size_t)(k0g+row)*MM + n0 + cq);
            Bs2[row][cq+0]=split_tf32(v.x); Bs2[row][cq+1]=split_tf32(v.y);
            Bs2[row][cq+2]=split_tf32(v.z); Bs2[row][cq+3]=split_tf32(v.w);
        }
        __syncthreads();
#pragma unroll
        for (int ks = 0; ks < 4; ks++) {
            int k0 = ks*8;
            uint2 a2[4][4], b2[4][2];
#pragma unroll
            for (int i = 0; i < 4; i++) {
                int mb = wm + i*16;
                a2[i][0] = As2[k0+c4  ][mb+r4];
                a2[i][1] = As2[k0+c4  ][mb+8+r4];
                a2[i][2] = As2[k0+4+c4][mb+r4];
                a2[i][3] = As2[k0+4+c4][mb+8+r4];
            }
#pragma unroll
            for (int j = 0; j < 4; j++) {
                int nb = wn + j*8;
                b2[j][0] = Bs2[k0+c4  ][nb+r4];
                b2[j][1] = Bs2[k0+4+c4][nb+r4];
            }
#pragma unroll
            for (int i = 0; i < 4; i++)
#pragma unroll
                for (int j = 0; j < 4; j++) mma_tf32x3(acc[i][j], a2[i], b2[j]);
        }
    }
    float* Pb = P + (size_t)z*MM*MM;
#pragma unroll
    for (int i = 0; i < 4; i++) {
        int row0 = m0 + wm + i*16 + r4;
#pragma unroll
        for (int j = 0; j < 4; j++) {
            int col = n0 + wn + j*8 + c4*2;
            *reinterpret_cast<float2*>(Pb + (size_t)row0*MM + col) =
                make_float2(acc[i][j].x, acc[i][j].y);
            *reinterpret_cast<float2*>(Pb + (size_t)(row0+8)*MM + col) =
                make_float2(acc[i][j].z, acc[i][j].w);
        }
    }
}

// Out = alpha*(P0+P1) + beta*Cadd
__global__ void ns_reduce_kernel(const float* __restrict__ P, const float* __restrict__ Cadd,
                                 float* __restrict__ Out, float alpha, float beta)
{
    size_t e = ((size_t)blockIdx.x * 256 + threadIdx.x) * 4;
    float4 p0 = *reinterpret_cast<const float4*>(P + e);
    float4 p1 = *reinterpret_cast<const float4*>(P + (size_t)BH*MM*MM + e);
    float4 v;
    v.x = alpha*(p0.x+p1.x); v.y = alpha*(p0.y+p1.y);
    v.z = alpha*(p0.z+p1.z); v.w = alpha*(p0.w+p1.w);
    if (Cadd) {
        float4 c = *reinterpret_cast<const float4*>(Cadd + e);
        v.x += beta*c.x; v.y += beta*c.y; v.z += beta*c.z; v.w += beta*c.w;
    }
    *reinterpret_cast<float4*>(Out + e) = v;
}

// ---------------- NN GEMM (small, for Y = inv @ RV) --------------------------
__global__ void __launch_bounds__(256) gemm_nn_kernel(
    const float* __restrict__ A, const float* __restrict__ B,
    float* __restrict__ Out, int Ma, int Nb, int Kd)
{
    __shared__ float As[64][65];
    __shared__ float Bs[64][65];
    int bh = blockIdx.z;
    int n0 = blockIdx.x * 64;
    int m0 = blockIdx.y * 64;
    const float* Ab = A + (size_t)bh*Ma*Kd;
    const float* Bb = B + (size_t)bh*Kd*Nb;
    float*       Ob = Out + (size_t)bh*Ma*Nb;
    int tid = threadIdx.x;
    int tx4 = (tid & 15) * 4, ty4 = (tid >> 4) * 4;
    float acc[4][4] = {};
    for (int k0 = 0; k0 < Kd; k0 += 64) {
        for (int l = tid; l < 64*16; l += 256) {
            int row = l >> 4, c4 = (l & 15) * 4;
            float4 va = *reinterpret_cast<const float4*>(Ab + (size_t)(m0+row)*Kd + k0 + c4);
            As[row][c4+0]=va.x; As[row][c4+1]=va.y; As[row][c4+2]=va.z; As[row][c4+3]=va.w;
            float4 vb = *reinterpret_cast<const float4*>(Bb + (size_t)(k0+row)*Nb + n0 + c4);
            Bs[row][c4+0]=vb.x; Bs[row][c4+1]=vb.y; Bs[row][c4+2]=vb.z; Bs[row][c4+3]=vb.w;
        }
        __syncthreads();
#pragma unroll 16
        for (int kk = 0; kk < 64; kk++) {
            float a0=As[ty4+0][kk], a1=As[ty4+1][kk], a2=As[ty4+2][kk], a3=As[ty4+3][kk];
            float b0=Bs[kk][tx4+0], b1=Bs[kk][tx4+1], b2=Bs[kk][tx4+2], b3=Bs[kk][tx4+3];
            acc[0][0]+=a0*b0; acc[0][1]+=a0*b1; acc[0][2]+=a0*b2; acc[0][3]+=a0*b3;
            acc[1][0]+=a1*b0; acc[1][1]+=a1*b1; acc[1][2]+=a1*b2; acc[1][3]+=a1*b3;
            acc[2][0]+=a2*b0; acc[2][1]+=a2*b1; acc[2][2]+=a2*b2; acc[2][3]+=a2*b3;
            acc[3][0]+=a3*b0; acc[3][1]+=a3*b1; acc[3][2]+=a3*b2; acc[3][3]+=a3*b3;
        }
        __syncthreads();
    }
#pragma unroll
    for (int i = 0; i < 4; i++) {
        size_t off = (size_t)(m0+ty4+i)*Nb + n0 + tx4;
        *reinterpret_cast<float4*>(Ob + off) =
            make_float4(acc[i][0], acc[i][1], acc[i][2], acc[i][3]);
    }
}

// ---------------- row softmax (in place), one block per row ------------------
__global__ void softmax_rows_kernel(float* __restrict__ data, int cols)
{
    extern __shared__ float buf[];
    __shared__ float red[256];
    size_t row = blockIdx.x;
    float* d = data + row * (size_t)cols;
    int tid = threadIdx.x;
    float mx = -FLT_MAX;
    for (int c = tid; c < cols; c += 256) { float v = d[c]; buf[c] = v; mx = fmaxf(mx, v); }
    red[tid] = mx; __syncthreads();
    for (int st = 128; st > 0; st >>= 1) { if (tid < st) red[tid] = fmaxf(red[tid], red[tid+st]); __syncthreads(); }
    mx = red[0];
    __syncthreads();
    float s = 0.f;
    for (int c = tid; c < cols; c += 256) { float e = __expf(buf[c] - mx); buf[c] = e; s += e; }
    red[tid] = s; __syncthreads();
    for (int st = 128; st > 0; st >>= 1) { if (tid < st) red[tid] += red[tid+st]; __syncthreads(); }
    float inv = 1.0f / red[0];
    for (int c = tid; c < cols; c += 256) d[c] = buf[c] * inv;
}

// ---------------- V0 = u^T / max_j(colsum_j(u)) ------------------------------
__global__ void __launch_bounds__(256) v0init_kernel(const float* __restrict__ U, float* __restrict__ V0)
{
    __shared__ float red[256];
    int bh = blockIdx.x;
    const float* u = U  + (size_t)bh*MM*MM;
    float*       v = V0 + (size_t)bh*MM*MM;
    int j = threadIdx.x;
    float s = 0.f;
    for (int i = 0; i < MM; i++) s += u[(size_t)i*MM + j];
    red[j] = s; __syncthreads();
    for (int st = 128; st > 0; st >>= 1) { if (j < st) red[j] = fmaxf(red[j], red[j+st]); __syncthreads(); }
    float scale = 1.0f / red[0];
    for (int q = 0; q < MM; q++) v[(size_t)j*MM + q] = scale * u[(size_t)q*MM + j];
}

// ---------------- RV split-K partials: 128x64 tile, 8x4 micro (fp32) ---------
__global__ void __launch_bounds__(256) rv_partial_kernel(
    const float* __restrict__ R, const float* __restrict__ Vv, float* __restrict__ P)
{
    extern __shared__ float sm[];
    float (*Rs)[68] = reinterpret_cast<float(*)[68]>(sm);
    float (*Vs)[68] = reinterpret_cast<float(*)[68]>(sm + 128*68);
    int s  = blockIdx.x;
    int m0 = blockIdx.y * 128;
    int bh = blockIdx.z;
    const float* Rb = R  + (size_t)bh*MM*NN;
    const float* Vb = Vv + (size_t)bh*NN*DD;
    int tid = threadIdx.x;
    int ry = (tid >> 4) * 8;
    int cx = (tid & 15) * 4;
    float acc[8][4] = {};
    for (int kc = 0; kc < 8; kc++) {
        int k0 = s*512 + kc*64;
        __syncthreads();
#pragma unroll
        for (int i = 0; i < 8; i++) {
            int idx = tid + i*256;
            int row = idx >> 4, c4 = (idx & 15) * 4;
            *reinterpret_cast<float4*>(&Rs[row][c4]) =
                *reinterpret_cast<const float4*>(Rb + (size_t)(m0+row)*NN + k0 + c4);
        }
#pragma unroll
        for (int i = 0; i < 4; i++) {
            int idx = tid + i*256;
            int row = idx >> 4, c4 = (idx & 15) * 4;
            *reinterpret_cast<float4*>(&Vs[row][c4]) =
                *reinterpret_cast<const float4*>(Vb + (size_t)(k0+row)*DD + c4);
        }
        __syncthreads();
#pragma unroll 8
        for (int kk = 0; kk < 64; kk++) {
            float b[4];
            *reinterpret_cast<float4*>(&b[0]) = *reinterpret_cast<float4*>(&Vs[kk][cx]);
            float a[8];
#pragma unroll
            for (int i = 0; i < 8; i++) a[i] = Rs[ry+i][kk];
#pragma unroll
            for (int i = 0; i < 8; i++)
#pragma unroll
                for (int j = 0; j < 4; j++) acc[i][j] += a[i]*b[j];
        }
    }
    float* Pb = P + ((size_t)s*BH + bh)*MM*DD;
#pragma unroll
    for (int i = 0; i < 8; i++)
        *reinterpret_cast<float4*>(Pb + (size_t)(m0+ry+i)*DD + cx) =
            make_float4(acc[i][0], acc[i][1], acc[i][2], acc[i][3]);
}

__global__ void rv_reduce_kernel(const float* __restrict__ P, float* __restrict__ RV)
{
    int e = blockIdx.x * 256 + threadIdx.x;
    float s = 0.f;
#pragma unroll
    for (int t = 0; t < 8; t++) s += P[(size_t)t*BH*MM*DD + e];
    RV[e] = s;
}

// ---------------- fused final: X_chunk = softmax(Qs_chunk @ nc^T) @ Y --------
#define FX_LPAD 260
__global__ void __launch_bounds__(256) fusedx_kernel(
    const float* __restrict__ Q, const float* __restrict__ nc,
    const float* __restrict__ Y, float* __restrict__ X)
{
    extern __shared__ float sm[];
    float (*As)[132] = reinterpret_cast<float(*)[132]>(sm);
    float (*Bs)[132] = reinterpret_cast<float(*)[132]>(sm + 64*132);
    float (*Ys)[68]  = reinterpret_cast<float(*)[68]> (sm + 64*132);
    float (*L)[FX_LPAD] = reinterpret_cast<float(*)[FX_LPAD]>(sm + 2*64*132);
    int bh = blockIdx.y;
    int q0 = blockIdx.x * 128;
    int tid = threadIdx.x;
    const float* Qb  = Q  + (size_t)bh*NN*DD;
    const float* ncb = nc + (size_t)bh*MM*DD;
    const float* Yb  = Y  + (size_t)bh*MM*DD;

#pragma unroll
    for (int i = 0; i < 8; i++) {
        int idx = tid + i*256;
        int row = idx & 127;
        int c4  = (idx >> 7) * 4;
        float4 v = *reinterpret_cast<const float4*>(Qb + (size_t)(q0+row)*DD + c4);
        As[c4+0][row]=v.x*0.125f; As[c4+1][row]=v.y*0.125f;
        As[c4+2][row]=v.z*0.125f; As[c4+3][row]=v.w*0.125f;
    }

    int tx8 = (tid & 15) * 8, ty8 = (tid >> 4) * 8;
    for (int cc = 0; cc < 2; cc++) {
        __syncthreads();
#pragma unroll
        for (int i = 0; i < 8; i++) {
            int idx = tid + i*256;
            int row = idx & 127;
            int c4  = (idx >> 7) * 4;
            float4 v = *reinterpret_cast<const float4*>(ncb + (size_t)(cc*128+row)*DD + c4);
            Bs[c4+0][row]=v.x; Bs[c4+1][row]=v.y; Bs[c4+2][row]=v.z; Bs[c4+3][row]=v.w;
        }
        __syncthreads();
        float acc[8][8] = {};
#pragma unroll 8
        for (int kk = 0; kk < 64; kk++) {
            float a[8], b[8];
            *reinterpret_cast<float4*>(&a[0]) = *reinterpret_cast<float4*>(&As[kk][ty8]);
            *reinterpret_cast<float4*>(&a[4]) = *reinterpret_cast<float4*>(&As[kk][ty8+4]);
            *reinterpret_cast<float4*>(&b[0]) = *reinterpret_cast<float4*>(&Bs[kk][tx8]);
            *reinterpret_cast<float4*>(&b[4]) = *reinterpret_cast<float4*>(&Bs[kk][tx8+4]);
#pragma unroll
            for (int i = 0; i < 8; i++)
#pragma unroll
                for (int j = 0; j < 8; j++) acc[i][j] += a[i]*b[j];
        }
#pragma unroll
        for (int i = 0; i < 8; i++) {
            *reinterpret_cast<float4*>(&L[ty8+i][cc*128+tx8]) =
                make_float4(acc[i][0],acc[i][1],acc[i][2],acc[i][3]);
            *reinterpret_cast<float4*>(&L[ty8+i][cc*128+tx8+4]) =
                make_float4(acc[i][4],acc[i][5],acc[i][6],acc[i][7]);
        }
    }
    __syncthreads();

    int wid = tid >> 5, lane = tid & 31;
    for (int r = wid; r < 128; r += 8) {
        float v[8]; float mx = -FLT_MAX;
#pragma unroll
        for (int t = 0; t < 8; t++) { v[t] = L[r][lane + 32*t]; mx = fmaxf(mx, v[t]); }
#pragma unroll
        for (int o = 16; o > 0; o >>= 1) mx = fmaxf(mx, __shfl_xor_sync(0xffffffffu, mx, o));
        float s = 0.f;
#pragma unroll
        for (int t = 0; t < 8; t++) { v[t] = __expf(v[t] - mx); s += v[t]; }
#pragma unroll
        for (int o = 16; o > 0; o >>= 1) s += __shfl_xor_sync(0xffffffffu, s, o);
        float inv = 1.0f / s;
#pragma unroll
        for (int t = 0; t < 8; t++) L[r][lane + 32*t] = v[t] * inv;
    }

    int ry = (tid >> 4) * 8;
    int cx = (tid & 15) * 4;
    float acc3[8][4] = {};
    for (int kc = 0; kc < 4; kc++) {
        __syncthreads();
#pragma unroll
        for (int i = 0; i < 4; i++) {
            int idx = tid + i*256;
            int row = idx >> 4, c4 = (idx & 15) * 4;
            *reinterpret_cast<float4*>(&Ys[row][c4]) =
                *reinterpret_cast<const float4*>(Yb + (size_t)(kc*64+row)*DD + c4);
        }
        __syncthreads();
#pragma unroll 8
        for (int kk = 0; kk < 64; kk++) {
            float b[4];
            *reinterpret_cast<float4*>(&b[0]) = *reinterpret_cast<float4*>(&Ys[kk][cx]);
            float a[8];
#pragma unroll
            for (int i = 0; i < 8; i++) a[i] = L[ry+i][kc*64+kk];
#pragma unroll
            for (int i = 0; i < 8; i++)
#pragma unroll
                for (int j = 0; j < 4; j++) acc3[i][j] += a[i]*b[j];
        }
    }
#pragma unroll
    for (int i = 0; i < 8; i++)
        *reinterpret_cast<float4*>(X + ((size_t)bh*NN + q0 + ry + i)*DD + cx) =
            make_float4(acc3[i][0], acc3[i][1], acc3[i][2], acc3[i][3]);
}

// ---------------- host launch ----------------
extern "C" void kernel_launch(void* const* d_in, const int* in_sizes, int n_in,
                              void* d_out, int out_size)
{
    (void)in_sizes; (void)n_in; (void)out_size;
    const float* Q = (const float*)d_in[0];
    const float* K = (const float*)d_in[1];
    const float* V = (const float*)d_in[2];
    float* X = (float*)d_out;

    static cudaStream_t s2 = nullptr;
    static cudaEvent_t evFork = nullptr, evJoin = nullptr;
    static bool attrs_done = false;
    if (!s2) {
        cudaStreamCreateWithFlags(&s2, cudaStreamNonBlocking);
        cudaEventCreateWithFlags(&evFork, cudaEventDisableTiming);
        cudaEventCreateWithFlags(&evJoin, cudaEventDisableTiming);
    }
    const int NT_SMEM  = 2*64*132*sizeof(float);                 // 67.5 KB
    const int RV_SMEM  = (128*68 + 64*68)*sizeof(float);         // 52.2 KB
    const int NS1_SMEM = 64*136*4 + 64*72*4;                     // 53.2 KB
    const int NS3_SMEM = 2*32*132*sizeof(uint2);                 // 67.6 KB
    const int FX_SMEM  = (2*64*132 + 128*FX_LPAD)*sizeof(float); // 200.7 KB
    if (!attrs_done) {
        cudaFuncSetAttribute(gemm_nt128_kernel, cudaFuncAttributeMaxDynamicSharedMemorySize, NT_SMEM);
        cudaFuncSetAttribute(rv_partial_kernel, cudaFuncAttributeMaxDynamicSharedMemorySize, RV_SMEM);
        cudaFuncSetAttribute(ns_fused1_kernel,  cudaFuncAttributeMaxDynamicSharedMemorySize, NS1_SMEM);
        cudaFuncSetAttribute(ns_tf32x3_kernel,  cudaFuncAttributeMaxDynamicSharedMemorySize, NS3_SMEM);
        cudaFuncSetAttribute(fusedx_kernel,     cudaFuncAttributeMaxDynamicSharedMemorySize, FX_SMEM);
        attrs_done = true;
    }

    float *nc, *nr, *u, *v0, *v1, *kv, *t1, *t2, *nsp, *r, *rvp, *rv, *y;
    int *ik, *iq;
    cudaGetSymbolAddress((void**)&nc, g_nc);
    cudaGetSymbolAddress((void**)&nr, g_nr);
    cudaGetSymbolAddress((void**)&ik, g_idxk);
    cudaGetSymbolAddress((void**)&iq, g_idxq);
    cudaGetSymbolAddress((void**)&u,  g_u);
    cudaGetSymbolAddress((void**)&v0, g_v0);
    cudaGetSymbolAddress((void**)&v1, g_v1);
    cudaGetSymbolAddress((void**)&kv, g_kv);
    cudaGetSymbolAddress((void**)&t1, g_t1);
    cudaGetSymbolAddress((void**)&t2, g_t2);
    cudaGetSymbolAddress((void**)&nsp, g_nsp);
    cudaGetSymbolAddress((void**)&r,  g_r);
    cudaGetSymbolAddress((void**)&rvp, g_rvp);
    cudaGetSymbolAddress((void**)&rv, g_rv);
    cudaGetSymbolAddress((void**)&y,  g_y);

    // 1) selection + gather
    topk_kernel<<<32, 1024>>>(Q, K, ik, iq);
    gather_kernel<<<16, dim3(64,4)>>>(Q, K, ik, iq, nc, nr);

    // fork: r-pipeline (fp32, FMA pipe) overlaps main-stream tensor work
    cudaEventRecord(evFork, 0);
    cudaStreamWaitEvent(s2, evFork, 0);

    gemm_nt128_kernel<<<dim3(NN/128, 2, 16), 256, NT_SMEM, s2>>>(nr, K, r, MM, NN);
    softmax_rows_kernel<<<BH*MM, 256, NN*sizeof(float), s2>>>(r, NN);
    rv_partial_kernel<<<dim3(8, 2, 16), 256, RV_SMEM, s2>>>(r, V, rvp);
    rv_reduce_kernel<<<BH*MM*DD/256, 256, 0, s2>>>(rvp, rv);
    cudaEventRecord(evJoin, s2);

    // main: u = softmax(nr @ nc^T); Newton-Schulz inverse
    gemm_nt128_kernel<<<dim3(2, 2, 16), 256, NT_SMEM>>>(nr, nc, u, MM, MM);
    softmax_rows_kernel<<<BH*MM, 256, MM*sizeof(float)>>>(u, MM);
    v0init_kernel<<<16, 256>>>(u, v0);

    const dim3 NSG(4, 2, 16);         // fused single-tf32 steps (iters 1-3)
    const int RB = BH*MM*MM/1024;     // reduce blocks (iter 4 split-K)
    float* vin = v0; float* vout = v1;
    for (int it = 0; it < 4; it++) {
        if (it < 3) {
            // single tf32, fused epilogue: Newton-Schulz self-corrects the noise
            ns_fused1_kernel<<<NSG, 256, NS1_SMEM>>>(u,   vin, nullptr, kv,   1.0f,  0.0f);
            ns_fused1_kernel<<<NSG, 256, NS1_SMEM>>>(kv,  kv,  kv,      t1,  -1.0f,  7.0f);
            ns_fused1_kernel<<<NSG, 256, NS1_SMEM>>>(kv,  t1,  kv,      t2,  -1.0f, 15.0f);
            ns_fused1_kernel<<<NSG, 256, NS1_SMEM>>>(vin, t2,  vin,     vout, -0.25f, 3.25f);
        } else {
            // final iteration fp32-grade (3xTF32 split-K + reduce): its noise
            // reaches the output directly
            ns_tf32x3_kernel<<<dim3(2,2,2*BH), 256, NS3_SMEM>>>(u, vin, nsp);
            ns_reduce_kernel<<<RB, 256>>>(nsp, nullptr, kv,  1.0f,  0.0f);
            ns_tf32x3_kernel<<<dim3(2,2,2*BH), 256, NS3_SMEM>>>(kv, kv, nsp);
            ns_reduce_kernel<<<RB, 256>>>(nsp, kv,      t1, -1.0f,  7.0f);
            ns_tf32x3_kernel<<<dim3(2,2,2*BH), 256, NS3_SMEM>>>(kv, t1, nsp);
            ns_reduce_kernel<<<RB, 256>>>(nsp, kv,      t2, -1.0f, 15.0f);
            ns_tf32x3_kernel<<<dim3(2,2,2*BH), 256, NS3_SMEM>>>(vin, t2, nsp);
            ns_reduce_kernel<<<RB, 256>>>(nsp, vin,     vout, -0.25f, 3.25f);
        }
        float* tmp = vin; vin = vout; vout = tmp;
    }

    // join: need rv before Y
    cudaStreamWaitEvent(0, evJoin, 0);

    // 7) Y = V_inv @ RV
    gemm_nn_kernel<<<dim3(1,4,16), 256>>>(vin, rv, y, MM, DD, MM);
    // 8) X = softmax(Qs @ nc^T) @ Y, fused per 128-row chunk
    fusedx_kernel<<<dim3(NN/128, BH), 256, FX_SMEM>>>(Q, nc, y, X);
}

// round 12
// speedup vs baseline: 1.1894x; 1.0107x over previous
#include <cuda_runtime.h>
#include <float.h>
#include <stdint.h>

#define BH 16
#define HH 8
#define NN 4096
#define DD 64
#define MM 256

// ---------------- scratch (__device__ globals; no allocation) ----------------
__device__ float g_nc [BH*MM*DD];
__device__ float g_nr [BH*MM*DD];
__device__ int   g_idxk[BH*MM];
__device__ int   g_idxq[BH*MM];
__device__ float g_u  [BH*MM*MM];
__device__ float g_v0 [BH*MM*MM];
__device__ float g_v1 [BH*MM*MM];
__device__ float g_kv [BH*MM*MM];
__device__ float g_t1 [BH*MM*MM];
__device__ float g_t2 [BH*MM*MM];
__device__ float g_rvp[8*BH*MM*DD];          // flash split partials
__device__ float g_ml [8*BH*MM*2];           // flash split (max, sumexp)
__device__ float g_rv [BH*MM*DD];
__device__ float g_y  [BH*MM*DD];

// ---------------- tf32 mma helpers ----------------
__device__ __forceinline__ uint32_t f2tf(float v) {
    uint32_t r; asm("cvt.rna.tf32.f32 %0, %1;" : "=r"(r) : "f"(v)); return r;
}
__device__ __forceinline__ void mma_tf32(float4& d, const uint32_t* a, const uint32_t* b) {
    asm volatile("mma.sync.aligned.m16n8k8.row.col.f32.tf32.tf32.f32 "
        "{%0,%1,%2,%3}, {%4,%5,%6,%7}, {%8,%9}, {%0,%1,%2,%3};"
        : "+f"(d.x), "+f"(d.y), "+f"(d.z), "+f"(d.w)
        : "r"(a[0]), "r"(a[1]), "r"(a[2]), "r"(a[3]), "r"(b[0]), "r"(b[1]));
}
__device__ __forceinline__ uint2 split_tf32(float x) {
    uint32_t hi = f2tf(x);
    float lo = x - __uint_as_float(hi);
    return make_uint2(hi, f2tf(lo));
}
// 3xTF32: d += a_hi*b_hi + a_lo*b_hi + a_hi*b_lo (fp32-grade)
__device__ __forceinline__ void mma_tf32x3(float4& d, const uint2* a, const uint2* b) {
    uint32_t ah[4] = {a[0].x, a[1].x, a[2].x, a[3].x};
    uint32_t al[4] = {a[0].y, a[1].y, a[2].y, a[3].y};
    uint32_t bh_[2] = {b[0].x, b[1].x};
    uint32_t bl_[2] = {b[0].y, b[1].y};
    mma_tf32(d, ah, bh_);
    mma_tf32(d, al, bh_);
    mma_tf32(d, ah, bl_);
}

// ---------------- top-k: exact bitonic sort of (sum,row) keys ----------------
__global__ void __launch_bounds__(1024) topk_kernel(
    const float* __restrict__ Q, const float* __restrict__ K,
    int* __restrict__ idxk, int* __restrict__ idxq)
{
    __shared__ unsigned long long keys[NN];
    int bh  = blockIdx.x >> 1;
    int isQ = blockIdx.x & 1;
    const float* src = isQ ? Q : K;
    int tid = threadIdx.x;

    for (int r = tid; r < NN; r += 1024) {
        const float4* p = reinterpret_cast<const float4*>(src + ((size_t)bh*NN + r)*DD);
        float s = 0.f;
#pragma unroll
        for (int t = 0; t < DD/4; t++) { float4 v = p[t]; s += v.x + v.y + v.z + v.w; }
        unsigned int u = __float_as_uint(s);
        unsigned int m = (u & 0x80000000u) ? ~u : (u | 0x80000000u);
        keys[r] = ((unsigned long long)(~m) << 32) | (unsigned int)r;
    }
    __syncthreads();

    for (int k = 2; k <= NN; k <<= 1) {
        for (int j = k >> 1; j > 0; j >>= 1) {
            for (int i = tid; i < NN; i += 1024) {
                int ixj = i ^ j;
                if (ixj > i) {
                    bool up = ((i & k) == 0);
                    unsigned long long a = keys[i], c = keys[ixj];
                    if ((a > c) == up) { keys[i] = c; keys[ixj] = a; }
                }
            }
            __syncthreads();
        }
    }
    int* dst = isQ ? idxq : idxk;
    if (tid < MM) dst[bh*MM + tid] = (int)(keys[tid] & 0xFFFFFFFFu);
}

// ---------------- gather nc = K[idx_k], nr = Q[idx_q]/8 ----------------
__global__ void gather_kernel(const float* __restrict__ Q, const float* __restrict__ K,
                              const int* __restrict__ idxk, const int* __restrict__ idxq,
                              float* __restrict__ nc, float* __restrict__ nr)
{
    int bh = blockIdx.x;
    int tx = threadIdx.x;
    int ty = threadIdx.y;
    for (int i = ty; i < MM; i += 4) {
        int ik = idxk[bh*MM + i];
        int iq = idxq[bh*MM + i];
        nc[((size_t)bh*MM + i)*DD + tx] = K[((size_t)bh*NN + ik)*DD + tx];
        nr[((size_t)bh*MM + i)*DD + tx] = Q[((size_t)bh*NN + iq)*DD + tx] * 0.125f;
    }
}

// ---------------- NT GEMM (K=64): 128x128 tile, 8x8 micro (fp32) -------------
__global__ void __launch_bounds__(256) gemm_nt128_kernel(
    const float* __restrict__ A, const float* __restrict__ B, float* __restrict__ C,
    int Ma, int Nb)
{
    extern __shared__ float sm[];
    float (*As)[132] = reinterpret_cast<float(*)[132]>(sm);
    float (*Bs)[132] = reinterpret_cast<float(*)[132]>(sm + 64*132);
    int bh = blockIdx.z;
    int m0 = blockIdx.y * 128;
    int n0 = blockIdx.x * 128;
    const float* Ab = A + (size_t)bh*Ma*64;
    const float* Bb = B + (size_t)bh*Nb*64;
    float*       Cb = C + (size_t)bh*Ma*Nb;
    int tid = threadIdx.x;
#pragma unroll
    for (int i = 0; i < 8; i++) {
        int idx = tid + i*256;
        int row = idx & 127;
        int c4  = (idx >> 7) * 4;
        float4 v = *reinterpret_cast<const float4*>(Ab + (size_t)(m0+row)*64 + c4);
        As[c4+0][row]=v.x; As[c4+1][row]=v.y; As[c4+2][row]=v.z; As[c4+3][row]=v.w;
        float4 w = *reinterpret_cast<const float4*>(Bb + (size_t)(n0+row)*64 + c4);
        Bs[c4+0][row]=w.x; Bs[c4+1][row]=w.y; Bs[c4+2][row]=w.z; Bs[c4+3][row]=w.w;
    }
    __syncthreads();
    int tx8 = (tid & 15) * 8, ty8 = (tid >> 4) * 8;
    float acc[8][8] = {};
#pragma unroll 8
    for (int kk = 0; kk < 64; kk++) {
        float a[8], b[8];
        *reinterpret_cast<float4*>(&a[0]) = *reinterpret_cast<float4*>(&As[kk][ty8]);
        *reinterpret_cast<float4*>(&a[4]) = *reinterpret_cast<float4*>(&As[kk][ty8+4]);
        *reinterpret_cast<float4*>(&b[0]) = *reinterpret_cast<float4*>(&Bs[kk][tx8]);
        *reinterpret_cast<float4*>(&b[4]) = *reinterpret_cast<float4*>(&Bs[kk][tx8+4]);
#pragma unroll
        for (int i = 0; i < 8; i++)
#pragma unroll
            for (int j = 0; j < 8; j++) acc[i][j] += a[i]*b[j];
    }
#pragma unroll
    for (int i = 0; i < 8; i++) {
        *reinterpret_cast<float4*>(Cb + (size_t)(m0+ty8+i)*Nb + n0+tx8) =
            make_float4(acc[i][0],acc[i][1],acc[i][2],acc[i][3]);
        *reinterpret_cast<float4*>(Cb + (size_t)(m0+ty8+i)*Nb + n0+tx8+4) =
            make_float4(acc[i][4],acc[i][5],acc[i][6],acc[i][7]);
    }
}

// ---------------- NS fused GEMM (single tf32, full K, fused epilogue) --------
// Out = alpha*(A@B) + beta*Cadd. Proven R8/R10/R11. grid (4, 2, 16).
__global__ void __launch_bounds__(256) ns_fused1_kernel(
    const float* __restrict__ A, const float* __restrict__ B,
    const float* __restrict__ Cadd, float* __restrict__ Out,
    float alpha, float beta)
{
    extern __shared__ char smc[];
    uint32_t (*As)[136] = reinterpret_cast<uint32_t(*)[136]>(smc);
    uint32_t (*Bs)[72]  = reinterpret_cast<uint32_t(*)[72]> (smc + 64*136*4);
    int bh = blockIdx.z;
    int n0 = blockIdx.x * 64;
    int m0 = blockIdx.y * 128;
    const float* Ab = A + (size_t)bh*MM*MM;
    const float* Bb = B + (size_t)bh*MM*MM;
    float*       Ob = Out + (size_t)bh*MM*MM;
    int tid = threadIdx.x, lane = tid & 31, wid = tid >> 5;
    int r4 = lane >> 2, c4 = lane & 3;
    int wm = (wid & 1) * 64;
    int wn = ((wid >> 1) & 1) * 32;
    int kg = wid >> 2;
    int kb = kg * 32;

    float4 acc[4][4];
#pragma unroll
    for (int i = 0; i < 4; i++)
#pragma unroll
        for (int j = 0; j < 4; j++) acc[i][j] = make_float4(0.f,0.f,0.f,0.f);

    for (int sc = 0; sc < 4; sc++) {
        int k0g = sc * 64;
        if (sc) __syncthreads();
#pragma unroll
        for (int i = 0; i < 8; i++) {
            int idx = tid + i*256;
            int row = idx & 127;
            int kq  = (idx >> 7) * 4;
            float4 v = *reinterpret_cast<const float4*>(Ab + (size_t)(m0+row)*MM + k0g + kq);
            As[kq+0][row]=f2tf(v.x); As[kq+1][row]=f2tf(v.y);
            As[kq+2][row]=f2tf(v.z); As[kq+3][row]=f2tf(v.w);
        }
#pragma unroll
        for (int i = 0; i < 4; i++) {
            int idx = tid + i*256;
            int row = idx >> 4;
            int cq  = (idx & 15) * 4;
            float4 v = *reinterpret_cast<const float4*>(Bb + (size_t)(k0g+row)*MM + n0 + cq);
            Bs[row][cq+0]=f2tf(v.x); Bs[row][cq+1]=f2tf(v.y);
            Bs[row][cq+2]=f2tf(v.z); Bs[row][cq+3]=f2tf(v.w);
        }
        __syncthreads();
#pragma unroll
        for (int ks = 0; ks < 4; ks++) {
            int k0 = kb + ks*8;
            uint32_t af[4][4], bf[4][2];
#pragma unroll
            for (int i = 0; i < 4; i++) {
                int mb = wm + i*16;
                af[i][0] = As[k0+c4  ][mb+r4];
                af[i][1] = As[k0+c4  ][mb+8+r4];
                af[i][2] = As[k0+4+c4][mb+r4];
                af[i][3] = As[k0+4+c4][mb+8+r4];
            }
#pragma unroll
            for (int j = 0; j < 4; j++) {
                int nb = wn + j*8;
                bf[j][0] = Bs[k0+c4  ][nb+r4];
                bf[j][1] = Bs[k0+4+c4][nb+r4];
            }
#pragma unroll
            for (int i = 0; i < 4; i++)
#pragma unroll
                for (int j = 0; j < 4; j++) mma_tf32(acc[i][j], af[i], bf[j]);
        }
    }

    __syncthreads();
    float4* red = reinterpret_cast<float4*>(smc);
    if (kg == 1) {
        int slot = wid - 4;
#pragma unroll
        for (int f = 0; f < 16; f++)
            red[((size_t)f*4 + slot)*32 + lane] = acc[f>>2][f&3];
    }
    __syncthreads();
    if (kg == 0) {
        const float* Cb = Cadd ? (Cadd + (size_t)bh*MM*MM) : nullptr;
#pragma unroll
        for (int f = 0; f < 16; f++) {
            float4 o = red[((size_t)f*4 + wid)*32 + lane];
            acc[f>>2][f&3].x += o.x; acc[f>>2][f&3].y += o.y;
            acc[f>>2][f&3].z += o.z; acc[f>>2][f&3].w += o.w;
        }
#pragma unroll
        for (int i = 0; i < 4; i++) {
            int row0 = m0 + wm + i*16 + r4;
#pragma unroll
            for (int j = 0; j < 4; j++) {
                int col = n0 + wn + j*8 + 2*c4;
                float2 v0 = make_float2(alpha*acc[i][j].x, alpha*acc[i][j].y);
                float2 v1 = make_float2(alpha*acc[i][j].z, alpha*acc[i][j].w);
                if (Cb) {
                    float2 c0 = *reinterpret_cast<const float2*>(Cb + (size_t)row0*MM + col);
                    float2 c1 = *reinterpret_cast<const float2*>(Cb + (size_t)(row0+8)*MM + col);
                    v0.x += beta*c0.x; v0.y += beta*c0.y;
                    v1.x += beta*c1.x; v1.y += beta*c1.y;
                }
                *reinterpret_cast<float2*>(Ob + (size_t)row0*MM + col) = v0;
                *reinterpret_cast<float2*>(Ob + (size_t)(row0+8)*MM + col) = v1;
            }
        }
    }
}

// ---------------- NS fused GEMM (3xTF32, fp32-grade; iteration 4) ------------
// Same structure as ns_fused1 (proven), uint2 hi/lo staging + mma_tf32x3.
__global__ void __launch_bounds__(256) ns_fused3_kernel(
    const float* __restrict__ A, const float* __restrict__ B,
    const float* __restrict__ Cadd, float* __restrict__ Out,
    float alpha, float beta)
{
    extern __shared__ char smc[];
    uint2 (*As2)[132] = reinterpret_cast<uint2(*)[132]>(smc);                 // [64k][132m]
    uint2 (*Bs2)[72]  = reinterpret_cast<uint2(*)[72]> (smc + 64*132*8);      // [64k][72n]
    int bh = blockIdx.z;
    int n0 = blockIdx.x * 64;
    int m0 = blockIdx.y * 128;
    const float* Ab = A + (size_t)bh*MM*MM;
    const float* Bb = B + (size_t)bh*MM*MM;
    float*       Ob = Out + (size_t)bh*MM*MM;
    int tid = threadIdx.x, lane = tid & 31, wid = tid >> 5;
    int r4 = lane >> 2, c4 = lane & 3;
    int wm = (wid & 1) * 64;
    int wn = ((wid >> 1) & 1) * 32;
    int kg = wid >> 2;
    int kb = kg * 32;

    float4 acc[4][4];
#pragma unroll
    for (int i = 0; i < 4; i++)
#pragma unroll
        for (int j = 0; j < 4; j++) acc[i][j] = make_float4(0.f,0.f,0.f,0.f);

    for (int sc = 0; sc < 4; sc++) {
        int k0g = sc * 64;
        if (sc) __syncthreads();
#pragma unroll
        for (int i = 0; i < 8; i++) {
            int idx = tid + i*256;
            int row = idx & 127;
            int kq  = (idx >> 7) * 4;
            float4 v = *reinterpret_cast<const float4*>(Ab + (size_t)(m0+row)*MM + k0g + kq);
            As2[kq+0][row]=split_tf32(v.x); As2[kq+1][row]=split_tf32(v.y);
            As2[kq+2][row]=split_tf32(v.z); As2[kq+3][row]=split_tf32(v.w);
        }
#pragma unroll
        for (int i = 0; i < 4; i++) {
            int idx = tid + i*256;
            int row = idx >> 4;
            int cq  = (idx & 15) * 4;
            float4 v = *reinterpret_cast<const float4*>(Bb + (size_t)(k0g+row)*MM + n0 + cq);
            Bs2[row][cq+0]=split_tf32(v.x); Bs2[row][cq+1]=split_tf32(v.y);
            Bs2[row][cq+2]=split_tf32(v.z); Bs2[row][cq+3]=split_tf32(v.w);
        }
        __syncthreads();
#pragma unroll
        for (int ks = 0; ks < 4; ks++) {
            int k0 = kb + ks*8;
            uint2 a2[4][4], b2[4][2];
#pragma unroll
            for (int i = 0; i < 4; i++) {
                int mb = wm + i*16;
                a2[i][0] = As2[k0+c4  ][mb+r4];
                a2[i][1] = As2[k0+c4  ][mb+8+r4];
                a2[i][2] = As2[k0+4+c4][mb+r4];
                a2[i][3] = As2[k0+4+c4][mb+8+r4];
            }
#pragma unroll
            for (int j = 0; j < 4; j++) {
                int nb = wn + j*8;
                b2[j][0] = Bs2[k0+c4  ][nb+r4];
                b2[j][1] = Bs2[k0+4+c4][nb+r4];
            }
#pragma unroll
            for (int i = 0; i < 4; i++)
#pragma unroll
                for (int j = 0; j < 4; j++) mma_tf32x3(acc[i][j], a2[i], b2[j]);
        }
    }

    __syncthreads();
    float4* red = reinterpret_cast<float4*>(smc);
    if (kg == 1) {
        int slot = wid - 4;
#pragma unroll
        for (int f = 0; f < 16; f++)
            red[((size_t)f*4 + slot)*32 + lane] = acc[f>>2][f&3];
    }
    __syncthreads();
    if (kg == 0) {
        const float* Cb = Cadd ? (Cadd + (size_t)bh*MM*MM) : nullptr;
#pragma unroll
        for (int f = 0; f < 16; f++) {
            float4 o = red[((size_t)f*4 + wid)*32 + lane];
            acc[f>>2][f&3].x += o.x; acc[f>>2][f&3].y += o.y;
            acc[f>>2][f&3].z += o.z; acc[f>>2][f&3].w += o.w;
        }
#pragma unroll
        for (int i = 0; i < 4; i++) {
            int row0 = m0 + wm + i*16 + r4;
#pragma unroll
            for (int j = 0; j < 4; j++) {
                int col = n0 + wn + j*8 + 2*c4;
                float2 v0 = make_float2(alpha*acc[i][j].x, alpha*acc[i][j].y);
                float2 v1 = make_float2(alpha*acc[i][j].z, alpha*acc[i][j].w);
                if (Cb) {
                    float2 c0 = *reinterpret_cast<const float2*>(Cb + (size_t)row0*MM + col);
                    float2 c1 = *reinterpret_cast<const float2*>(Cb + (size_t)(row0+8)*MM + col);
                    v0.x += beta*c0.x; v0.y += beta*c0.y;
                    v1.x += beta*c1.x; v1.y += beta*c1.y;
                }
                *reinterpret_cast<float2*>(Ob + (size_t)row0*MM + col) = v0;
                *reinterpret_cast<float2*>(Ob + (size_t)(row0+8)*MM + col) = v1;
            }
        }
    }
}

// ---------------- NN GEMM (small, for Y = inv @ RV) --------------------------
__global__ void __launch_bounds__(256) gemm_nn_kernel(
    const float* __restrict__ A, const float* __restrict__ B,
    float* __restrict__ Out, int Ma, int Nb, int Kd)
{
    __shared__ float As[64][65];
    __shared__ float Bs[64][65];
    int bh = blockIdx.z;
    int n0 = blockIdx.x * 64;
    int m0 = blockIdx.y * 64;
    const float* Ab = A + (size_t)bh*Ma*Kd;
    const float* Bb = B + (size_t)bh*Kd*Nb;
    float*       Ob = Out + (size_t)bh*Ma*Nb;
    int tid = threadIdx.x;
    int tx4 = (tid & 15) * 4, ty4 = (tid >> 4) * 4;
    float acc[4][4] = {};
    for (int k0 = 0; k0 < Kd; k0 += 64) {
        for (int l = tid; l < 64*16; l += 256) {
            int row = l >> 4, c4 = (l & 15) * 4;
            float4 va = *reinterpret_cast<const float4*>(Ab + (size_t)(m0+row)*Kd + k0 + c4);
            As[row][c4+0]=va.x; As[row][c4+1]=va.y; As[row][c4+2]=va.z; As[row][c4+3]=va.w;
            float4 vb = *reinterpret_cast<const float4*>(Bb + (size_t)(k0+row)*Nb + n0 + c4);
            Bs[row][c4+0]=vb.x; Bs[row][c4+1]=vb.y; Bs[row][c4+2]=vb.z; Bs[row][c4+3]=vb.w;
        }
        __syncthreads();
#pragma unroll 16
        for (int kk = 0; kk < 64; kk++) {
            float a0=As[ty4+0][kk], a1=As[ty4+1][kk], a2=As[ty4+2][kk], a3=As[ty4+3][kk];
            float b0=Bs[kk][tx4+0], b1=Bs[kk][tx4+1], b2=Bs[kk][tx4+2], b3=Bs[kk][tx4+3];
            acc[0][0]+=a0*b0; acc[0][1]+=a0*b1; acc[0][2]+=a0*b2; acc[0][3]+=a0*b3;
            acc[1][0]+=a1*b0; acc[1][1]+=a1*b1; acc[1][2]+=a1*b2; acc[1][3]+=a1*b3;
            acc[2][0]+=a2*b0; acc[2][1]+=a2*b1; acc[2][2]+=a2*b2; acc[2][3]+=a2*b3;
            acc[3][0]+=a3*b0; acc[3][1]+=a3*b1; acc[3][2]+=a3*b2; acc[3][3]+=a3*b3;
        }
        __syncthreads();
    }
#pragma unroll
    for (int i = 0; i < 4; i++) {
        size_t off = (size_t)(m0+ty4+i)*Nb + n0 + tx4;
        *reinterpret_cast<float4*>(Ob + off) =
            make_float4(acc[i][0], acc[i][1], acc[i][2], acc[i][3]);
    }
}

// ---------------- row softmax (in place), one block per row ------------------
__global__ void softmax_rows_kernel(float* __restrict__ data, int cols)
{
    extern __shared__ float buf[];
    __shared__ float red[256];
    size_t row = blockIdx.x;
    float* d = data + row * (size_t)cols;
    int tid = threadIdx.x;
    float mx = -FLT_MAX;
    for (int c = tid; c < cols; c += 256) { float v = d[c]; buf[c] = v; mx = fmaxf(mx, v); }
    red[tid] = mx; __syncthreads();
    for (int st = 128; st > 0; st >>= 1) { if (tid < st) red[tid] = fmaxf(red[tid], red[tid+st]); __syncthreads(); }
    mx = red[0];
    __syncthreads();
    float s = 0.f;
    for (int c = tid; c < cols; c += 256) { float e = __expf(buf[c] - mx); buf[c] = e; s += e; }
    red[tid] = s; __syncthreads();
    for (int st = 128; st > 0; st >>= 1) { if (tid < st) red[tid] += red[tid+st]; __syncthreads(); }
    float inv = 1.0f / red[0];
    for (int c = tid; c < cols; c += 256) d[c] = buf[c] * inv;
}

// ---------------- V0 = u^T / max_j(colsum_j(u)) ------------------------------
__global__ void __launch_bounds__(256) v0init_kernel(const float* __restrict__ U, float* __restrict__ V0)
{
    __shared__ float red[256];
    int bh = blockIdx.x;
    const float* u = U  + (size_t)bh*MM*MM;
    float*       v = V0 + (size_t)bh*MM*MM;
    int j = threadIdx.x;
    float s = 0.f;
    for (int i = 0; i < MM; i++) s += u[(size_t)i*MM + j];
    red[j] = s; __syncthreads();
    for (int st = 128; st > 0; st >>= 1) { if (j < st) red[j] = fmaxf(red[j], red[j+st]); __syncthreads(); }
    float scale = 1.0f / red[0];
    for (int q = 0; q < MM; q++) v[(size_t)j*MM + q] = scale * u[(size_t)q*MM + j];
}

// ---------------- flash RV: partial softmax(nr @ K^T) @ V over KV splits -----
// Each block: 128 nr rows x 512 KV (8 chunks of 64), online softmax.
// Outputs unnormalized O plus per-row (max, sumexp). grid (8, 2, 16).
__global__ void __launch_bounds__(256) rv_flash_kernel(
    const float* __restrict__ NR, const float* __restrict__ K,
    const float* __restrict__ V, float* __restrict__ P, float* __restrict__ ML)
{
    extern __shared__ float sm[];
    float (*Nrs)[68] = reinterpret_cast<float(*)[68]>(sm);                 // [128m][68k]
    float (*Ksk)[68] = reinterpret_cast<float(*)[68]>(sm + 128*68);        // [64k][68c]  (k-major)
    float (*Vs)[68]  = reinterpret_cast<float(*)[68]>(sm + 128*68 + 64*68);// [64kv][68d]
    float (*Ps)[68]  = reinterpret_cast<float(*)[68]>(sm + 128*68 + 2*64*68); // [128m][68c]
    int s  = blockIdx.x;
    int m0 = blockIdx.y * 128;
    int bh = blockIdx.z;
    const float* Nb = NR + (size_t)bh*MM*DD;
    const float* Kb = K  + (size_t)bh*NN*DD;
    const float* Vb = V  + (size_t)bh*NN*DD;
    int tid = threadIdx.x;
    int ry = (tid >> 4) * 8;   // 8 rows
    int cx = (tid & 15) * 4;   // 4 cols

    // stage nr rows (row-major)
#pragma unroll
    for (int i = 0; i < 8; i++) {
        int idx = tid + i*256;
        int row = idx >> 4, q4 = (idx & 15) * 4;
        *reinterpret_cast<float4*>(&Nrs[row][q4]) =
            *reinterpret_cast<const float4*>(Nb + (size_t)(m0+row)*DD + q4);
    }

    float m_i[8], l_i[8];
    float O[8][4] = {};
#pragma unroll
    for (int i = 0; i < 8; i++) { m_i[i] = -FLT_MAX; l_i[i] = 0.f; }

    for (int kc = 0; kc < 8; kc++) {
        int k0 = s*512 + kc*64;
        __syncthreads();   // protects Ksk/Vs reuse and Ps from previous GEMM2
        // K chunk, transposed to k-major: Ksk[feat][c]
#pragma unroll
        for (int i = 0; i < 4; i++) {
            int idx = tid + i*256;
            int c  = idx & 63;
            int kq = (idx >> 6) * 4;
            float4 v = *reinterpret_cast<const float4*>(Kb + (size_t)(k0+c)*DD + kq);
            Ksk[kq+0][c]=v.x; Ksk[kq+1][c]=v.y; Ksk[kq+2][c]=v.z; Ksk[kq+3][c]=v.w;
        }
        // V chunk, row-major
#pragma unroll
        for (int i = 0; i < 4; i++) {
            int idx = tid + i*256;
            int row = idx >> 4, q4 = (idx & 15) * 4;
            *reinterpret_cast<float4*>(&Vs[row][q4]) =
                *reinterpret_cast<const float4*>(Vb + (size_t)(k0+row)*DD + q4);
        }
        __syncthreads();

        // GEMM1: S[128][64] = Nrs @ Ksk
        float sv[8][4] = {};
#pragma unroll 8
        for (int kk = 0; kk < 64; kk++) {
            float b[4];
            *reinterpret_cast<float4*>(&b[0]) = *reinterpret_cast<float4*>(&Ksk[kk][cx]);
            float a[8];
#pragma unroll
            for (int i = 0; i < 8; i++) a[i] = Nrs[ry+i][kk];
#pragma unroll
            for (int i = 0; i < 8; i++)
#pragma unroll
                for (int j = 0; j < 4; j++) sv[i][j] += a[i]*b[j];
        }

        // online softmax update per row (16 lanes per row share via shuffle)
#pragma unroll
        for (int i = 0; i < 8; i++) {
            float mc = fmaxf(fmaxf(sv[i][0], sv[i][1]), fmaxf(sv[i][2], sv[i][3]));
#pragma unroll
            for (int o = 8; o > 0; o >>= 1) mc = fmaxf(mc, __shfl_xor_sync(0xffffffffu, mc, o));
            float mn = fmaxf(m_i[i], mc);
            float corr = __expf(m_i[i] - mn);
            l_i[i] *= corr;
#pragma unroll
            for (int j = 0; j < 4; j++) O[i][j] *= corr;
            float ls = 0.f;
#pragma unroll
            for (int j = 0; j < 4; j++) {
                float p = __expf(sv[i][j] - mn);
                Ps[ry+i][cx+j] = p;
                ls += p;
            }
#pragma unroll
            for (int o = 8; o > 0; o >>= 1) ls += __shfl_xor_sync(0xffffffffu, ls, o);
            l_i[i] += ls;
            m_i[i] = mn;
        }
        __syncthreads();

        // GEMM2: O += Ps(128x64) @ Vs(64x64)
#pragma unroll 8
        for (int kk = 0; kk < 64; kk++) {
            float b[4];
            *reinterpret_cast<float4*>(&b[0]) = *reinterpret_cast<float4*>(&Vs[kk][cx]);
            float a[8];
#pragma unroll
            for (int i = 0; i < 8; i++) a[i] = Ps[ry+i][kk];
#pragma unroll
            for (int i = 0; i < 8; i++)
#pragma unroll
                for (int j = 0; j < 4; j++) O[i][j] += a[i]*b[j];
        }
    }

    float* Pb = P + ((size_t)s*BH + bh)*MM*DD;
#pragma unroll
    for (int i = 0; i < 8; i++)
        *reinterpret_cast<float4*>(Pb + (size_t)(m0+ry+i)*DD + cx) =
            make_float4(O[i][0], O[i][1], O[i][2], O[i][3]);
    if ((tid & 15) == 0) {
        float* mlb = ML + (((size_t)s*BH + bh)*MM + m0)*2;
#pragma unroll
        for (int i = 0; i < 8; i++) {
            mlb[(ry+i)*2 + 0] = m_i[i];
            mlb[(ry+i)*2 + 1] = l_i[i];
        }
    }
}

// combine 8 splits: rv = (sum_s w_s * O_s) / (sum_s w_s * l_s), w_s = exp(m_s - gm)
__global__ void rv_combine_kernel(const float* __restrict__ P, const float* __restrict__ ML,
                                  float* __restrict__ RV)
{
    int gt = blockIdx.x * 256 + threadIdx.x;    // 65536 threads: (row, 4cols)
    int row = gt >> 4;                           // 0..4095 = bh*256 + r
    int c4  = (gt & 15) * 4;
    float m_s[8], l_s[8];
    float gm = -FLT_MAX;
#pragma unroll
    for (int s = 0; s < 8; s++) {
        m_s[s] = ML[(((size_t)s*BH*MM) + row)*2 + 0];
        l_s[s] = ML[(((size_t)s*BH*MM) + row)*2 + 1];
        gm = fmaxf(gm, m_s[s]);
    }
    float L = 0.f;
    float4 acc = make_float4(0.f,0.f,0.f,0.f);
#pragma unroll
    for (int s = 0; s < 8; s++) {
        float w = __expf(m_s[s] - gm);
        L += w * l_s[s];
        float4 o = *reinterpret_cast<const float4*>(P + ((size_t)s*BH*MM + row)*DD + c4);
        acc.x += w*o.x; acc.y += w*o.y; acc.z += w*o.z; acc.w += w*o.w;
    }
    float inv = 1.0f / L;
    *reinterpret_cast<float4*>(RV + (size_t)row*DD + c4) =
        make_float4(acc.x*inv, acc.y*inv, acc.z*inv, acc.w*inv);
}

// ---------------- fused final: X_chunk = softmax(Qs_chunk @ nc^T) @ Y --------
#define FX_LPAD 260
__global__ void __launch_bounds__(256) fusedx_kernel(
    const float* __restrict__ Q, const float* __restrict__ nc,
    const float* __restrict__ Y, float* __restrict__ X)
{
    extern __shared__ float sm[];
    float (*As)[132] = reinterpret_cast<float(*)[132]>(sm);
    float (*Bs)[132] = reinterpret_cast<float(*)[132]>(sm + 64*132);
    float (*Ys)[68]  = reinterpret_cast<float(*)[68]> (sm + 64*132);
    float (*L)[FX_LPAD] = reinterpret_cast<float(*)[FX_LPAD]>(sm + 2*64*132);
    int bh = blockIdx.y;
    int q0 = blockIdx.x * 128;
    int tid = threadIdx.x;
    const float* Qb  = Q  + (size_t)bh*NN*DD;
    const float* ncb = nc + (size_t)bh*MM*DD;
    const float* Yb  = Y  + (size_t)bh*MM*DD;

#pragma unroll
    for (int i = 0; i < 8; i++) {
        int idx = tid + i*256;
        int row = idx & 127;
        int c4  = (idx >> 7) * 4;
        float4 v = *reinterpret_cast<const float4*>(Qb + (size_t)(q0+row)*DD + c4);
        As[c4+0][row]=v.x*0.125f; As[c4+1][row]=v.y*0.125f;
        As[c4+2][row]=v.z*0.125f; As[c4+3][row]=v.w*0.125f;
    }

    int tx8 = (tid & 15) * 8, ty8 = (tid >> 4) * 8;
    for (int cc = 0; cc < 2; cc++) {
        __syncthreads();
#pragma unroll
        for (int i = 0; i < 8; i++) {
            int idx = tid + i*256;
            int row = idx & 127;
            int c4  = (idx >> 7) * 4;
            float4 v = *reinterpret_cast<const float4*>(ncb + (size_t)(cc*128+row)*DD + c4);
            Bs[c4+0][row]=v.x; Bs[c4+1][row]=v.y; Bs[c4+2][row]=v.z; Bs[c4+3][row]=v.w;
        }
        __syncthreads();
        float acc[8][8] = {};
#pragma unroll 8
        for (int kk = 0; kk < 64; kk++) {
            float a[8], b[8];
            *reinterpret_cast<float4*>(&a[0]) = *reinterpret_cast<float4*>(&As[kk][ty8]);
            *reinterpret_cast<float4*>(&a[4]) = *reinterpret_cast<float4*>(&As[kk][ty8+4]);
            *reinterpret_cast<float4*>(&b[0]) = *reinterpret_cast<float4*>(&Bs[kk][tx8]);
            *reinterpret_cast<float4*>(&b[4]) = *reinterpret_cast<float4*>(&Bs[kk][tx8+4]);
#pragma unroll
            for (int i = 0; i < 8; i++)
#pragma unroll
                for (int j = 0; j < 8; j++) acc[i][j] += a[i]*b[j];
        }
#pragma unroll
        for (int i = 0; i < 8; i++) {
            *reinterpret_cast<float4*>(&L[ty8+i][cc*128+tx8]) =
                make_float4(acc[i][0],acc[i][1],acc[i][2],acc[i][3]);
            *reinterpret_cast<float4*>(&L[ty8+i][cc*128+tx8+4]) =
                make_float4(acc[i][4],acc[i][5],acc[i][6],acc[i][7]);
        }
    }
    __syncthreads();

    int wid = tid >> 5, lane = tid & 31;
    for (int r = wid; r < 128; r += 8) {
        float v[8]; float mx = -FLT_MAX;
#pragma unroll
        for (int t = 0; t < 8; t++) { v[t] = L[r][lane + 32*t]; mx = fmaxf(mx, v[t]); }
#pragma unroll
        for (int o = 16; o > 0; o >>= 1) mx = fmaxf(mx, __shfl_xor_sync(0xffffffffu, mx, o));
        float s = 0.f;
#pragma unroll
        for (int t = 0; t < 8; t++) { v[t] = __expf(v[t] - mx); s += v[t]; }
#pragma unroll
        for (int o = 16; o > 0; o >>= 1) s += __shfl_xor_sync(0xffffffffu, s, o);
        float inv = 1.0f / s;
#pragma unroll
        for (int t = 0; t < 8; t++) L[r][lane + 32*t] = v[t] * inv;
    }

    int ry = (tid >> 4) * 8;
    int cx = (tid & 15) * 4;
    float acc3[8][4] = {};
    for (int kc = 0; kc < 4; kc++) {
        __syncthreads();
#pragma unroll
        for (int i = 0; i < 4; i++) {
            int idx = tid + i*256;
            int row = idx >> 4, c4 = (idx & 15) * 4;
            *reinterpret_cast<float4*>(&Ys[row][c4]) =
                *reinterpret_cast<const float4*>(Yb + (size_t)(kc*64+row)*DD + c4);
        }
        __syncthreads();
#pragma unroll 8
        for (int kk = 0; kk < 64; kk++) {
            float b[4];
            *reinterpret_cast<float4*>(&b[0]) = *reinterpret_cast<float4*>(&Ys[kk][cx]);
            float a[8];
#pragma unroll
            for (int i = 0; i < 8; i++) a[i] = L[ry+i][kc*64+kk];
#pragma unroll
            for (int i = 0; i < 8; i++)
#pragma unroll
                for (int j = 0; j < 4; j++) acc3[i][j] += a[i]*b[j];
        }
    }
#pragma unroll
    for (int i = 0; i < 8; i++)
        *reinterpret_cast<float4*>(X + ((size_t)bh*NN + q0 + ry + i)*DD + cx) =
            make_float4(acc3[i][0], acc3[i][1], acc3[i][2], acc3[i][3]);
}

// ---------------- host launch ----------------
extern "C" void kernel_launch(void* const* d_in, const int* in_sizes, int n_in,
                              void* d_out, int out_size)
{
    (void)in_sizes; (void)n_in; (void)out_size;
    const float* Q = (const float*)d_in[0];
    const float* K = (const float*)d_in[1];
    const float* V = (const float*)d_in[2];
    float* X = (float*)d_out;

    static cudaStream_t s2 = nullptr;
    static cudaEvent_t evFork = nullptr, evJoin = nullptr;
    static bool attrs_done = false;
    if (!s2) {
        cudaStreamCreateWithFlags(&s2, cudaStreamNonBlocking);
        cudaEventCreateWithFlags(&evFork, cudaEventDisableTiming);
        cudaEventCreateWithFlags(&evJoin, cudaEventDisableTiming);
    }
    const int NT_SMEM  = 2*64*132*sizeof(float);                 // 67.5 KB
    const int NS1_SMEM = 64*136*4 + 64*72*4;                     // 53.2 KB
    const int NS3_SMEM = 64*132*8 + 64*72*8;                     // 104.4 KB
    const int FL_SMEM  = (128*68 + 64*68 + 64*68 + 128*68)*4;    // 104.4 KB
    const int FX_SMEM  = (2*64*132 + 128*FX_LPAD)*sizeof(float); // 200.7 KB
    if (!attrs_done) {
        cudaFuncSetAttribute(gemm_nt128_kernel, cudaFuncAttributeMaxDynamicSharedMemorySize, NT_SMEM);
        cudaFuncSetAttribute(ns_fused1_kernel,  cudaFuncAttributeMaxDynamicSharedMemorySize, NS1_SMEM);
        cudaFuncSetAttribute(ns_fused3_kernel,  cudaFuncAttributeMaxDynamicSharedMemorySize, NS3_SMEM);
        cudaFuncSetAttribute(rv_flash_kernel,   cudaFuncAttributeMaxDynamicSharedMemorySize, FL_SMEM);
        cudaFuncSetAttribute(fusedx_kernel,     cudaFuncAttributeMaxDynamicSharedMemorySize, FX_SMEM);
        attrs_done = true;
    }

    float *nc, *nr, *u, *v0, *v1, *kv, *t1, *t2, *rvp, *ml, *rv, *y;
    int *ik, *iq;
    cudaGetSymbolAddress((void**)&nc, g_nc);
    cudaGetSymbolAddress((void**)&nr, g_nr);
    cudaGetSymbolAddress((void**)&ik, g_idxk);
    cudaGetSymbolAddress((void**)&iq, g_idxq);
    cudaGetSymbolAddress((void**)&u,  g_u);
    cudaGetSymbolAddress((void**)&v0, g_v0);
    cudaGetSymbolAddress((void**)&v1, g_v1);
    cudaGetSymbolAddress((void**)&kv, g_kv);
    cudaGetSymbolAddress((void**)&t1, g_t1);
    cudaGetSymbolAddress((void**)&t2, g_t2);
    cudaGetSymbolAddress((void**)&rvp, g_rvp);
    cudaGetSymbolAddress((void**)&ml, g_ml);
    cudaGetSymbolAddress((void**)&rv, g_rv);
    cudaGetSymbolAddress((void**)&y,  g_y);

    // 1) selection + gather
    topk_kernel<<<32, 1024>>>(Q, K, ik, iq);
    gather_kernel<<<16, dim3(64,4)>>>(Q, K, ik, iq, nc, nr);

    // fork: flash RV pipeline (fp32, FMA pipe) overlaps main-stream tensor work
    cudaEventRecord(evFork, 0);
    cudaStreamWaitEvent(s2, evFork, 0);

    rv_flash_kernel<<<dim3(8, 2, 16), 256, FL_SMEM, s2>>>(nr, K, V, rvp, ml);
    rv_combine_kernel<<<BH*MM*DD/(256*4), 256, 0, s2>>>(rvp, ml, rv);
    cudaEventRecord(evJoin, s2);

    // main: u = softmax(nr @ nc^T); Newton-Schulz inverse
    gemm_nt128_kernel<<<dim3(2, 2, 16), 256, NT_SMEM>>>(nr, nc, u, MM, MM);
    softmax_rows_kernel<<<BH*MM, 256, MM*sizeof(float)>>>(u, MM);
    v0init_kernel<<<16, 256>>>(u, v0);

    const dim3 NSG(4, 2, 16);
    float* vin = v0; float* vout = v1;
    for (int it = 0; it < 4; it++) {
        if (it < 3) {
            // single tf32, fused epilogue: Newton-Schulz self-corrects the noise
            ns_fused1_kernel<<<NSG, 256, NS1_SMEM>>>(u,   vin, nullptr, kv,   1.0f,  0.0f);
            ns_fused1_kernel<<<NSG, 256, NS1_SMEM>>>(kv,  kv,  kv,      t1,  -1.0f,  7.0f);
            ns_fused1_kernel<<<NSG, 256, NS1_SMEM>>>(kv,  t1,  kv,      t2,  -1.0f, 15.0f);
            ns_fused1_kernel<<<NSG, 256, NS1_SMEM>>>(vin, t2,  vin,     vout, -0.25f, 3.25f);
        } else {
            // final iteration fp32-grade (3xTF32, fused epilogue)
            ns_fused3_kernel<<<NSG, 256, NS3_SMEM>>>(u,   vin, nullptr, kv,   1.0f,  0.0f);
            ns_fused3_kernel<<<NSG, 256, NS3_SMEM>>>(kv,  kv,  kv,      t1,  -1.0f,  7.0f);
            ns_fused3_kernel<<<NSG, 256, NS3_SMEM>>>(kv,  t1,  kv,      t2,  -1.0f, 15.0f);
            ns_fused3_kernel<<<NSG, 256, NS3_SMEM>>>(vin, t2,  vin,     vout, -0.25f, 3.25f);
        }
        float* tmp = vin; vin = vout; vout = tmp;
    }

    // join: need rv before Y
    cudaStreamWaitEvent(0, evJoin, 0);

    // 7) Y = V_inv @ RV
    gemm_nn_kernel<<<dim3(1,4,16), 256>>>(vin, rv, y, MM, DD, MM);
    // 8) X = softmax(Qs @ nc^T) @ Y, fused per 128-row chunk
    fusedx_kernel<<<dim3(NN/128, BH), 256, FX_SMEM>>>(Q, nc, y, X);
}